// round 15
// baseline (speedup 1.0000x reference)
#include <cuda_runtime.h>
#include <cuda_bf16.h>
#include <cstdint>
#include <cstddef>

#define Nn 20000
#define Ee 320000
#define Ff 128
#define Hh 8
#define EFe 64
#define Aa 128
#define Gg 32
#define F2 256
#define NTILE 128
#define ETILE 128
#define NTILES (Ee / ETILE)

// ---------------- scratch (device globals; no allocations allowed) ----------------
__device__ float g_sb_mix[Gg * F2];
__device__ float g_sb_mlp[Gg * F2];
__device__ __nv_bfloat16 g_hsrcB[(size_t)Nn * Ff];   // bf16 now
__device__ __nv_bfloat16 g_hdstB[(size_t)Nn * Ff];
__device__ float g_wsum[Nn * Hh];
__device__ float g_o[(size_t)Nn * Ff];
// prepacked bf16 transposed weights
__device__ __nv_bfloat16 pbH[256 * 128];
__device__ __nv_bfloat16 pbO[128 * 128];
__device__ __nv_bfloat16 pb1[512 * 128];
__device__ __nv_bfloat16 pb2[128 * 512];

__device__ __forceinline__ float siluf(float x) { return x / (1.f + __expf(-x)); }

__device__ __forceinline__ void mma_bf16(float* d, uint32_t a0, uint32_t a1,
                                         uint32_t a2, uint32_t a3,
                                         uint32_t b0, uint32_t b1) {
    asm volatile(
        "mma.sync.aligned.m16n8k16.row.col.f32.bf16.bf16.f32 "
        "{%0,%1,%2,%3}, {%4,%5,%6,%7}, {%8,%9}, {%0,%1,%2,%3};"
        : "+f"(d[0]), "+f"(d[1]), "+f"(d[2]), "+f"(d[3])
        : "r"(a0), "r"(a1), "r"(a2), "r"(a3), "r"(b0), "r"(b1));
}

__device__ __forceinline__ void ldsm_x4(uint32_t& r0, uint32_t& r1,
                                        uint32_t& r2, uint32_t& r3, uint32_t addr) {
    asm volatile("ldmatrix.sync.aligned.m8n8.x4.shared.b16 {%0,%1,%2,%3}, [%4];"
                 : "=r"(r0), "=r"(r1), "=r"(r2), "=r"(r3) : "r"(addr));
}
__device__ __forceinline__ void ldsm_x2(uint32_t& r0, uint32_t& r1, uint32_t addr) {
    asm volatile("ldmatrix.sync.aligned.m8n8.x2.shared.b16 {%0,%1}, [%2];"
                 : "=r"(r0), "=r"(r1) : "r"(addr));
}

__device__ __forceinline__ void cp16(uint32_t dst, const void* src) {
    asm volatile("cp.async.cg.shared.global [%0], [%1], 16;" :: "r"(dst), "l"(src));
}
#define CP_COMMIT() asm volatile("cp.async.commit_group;" ::: "memory")
#define CP_WAIT(N)  asm volatile("cp.async.wait_group %0;" :: "n"(N) : "memory")

__device__ __forceinline__ uint32_t pack_bf16(float a, float b) {
    __nv_bfloat162 p = __floats2bfloat162_rn(a, b);
    return *(uint32_t*)&p;
}
__device__ __forceinline__ float2 unpack_bf16(uint32_t u) {
    __nv_bfloat162 p = *(__nv_bfloat162*)&u;
    return make_float2(__bfloat162float(p.x), __bfloat162float(p.y));
}

// ---------------- init: zero accumulators ----------------------------------------
__global__ void k_init() {
    int i = blockIdx.x * 256 + threadIdx.x;
    if (i < Nn * Ff) g_o[i] = 0.f;
    if (i < Nn * Hh) g_wsum[i] = 0.f;
}

// ---------------- k_prep: tiled-transpose weights into bf16 [n][k] ----------------
__global__ __launch_bounds__(256) void k_prep(const float* __restrict__ w_h,
                                              const float* __restrict__ w_out,
                                              const float* __restrict__ w1,
                                              const float* __restrict__ w2) {
    __shared__ float t[32][33];
    int b = blockIdx.x;
    const float* src; __nv_bfloat16* dst; int K, N, tk, tn;
    if (b < 32)       { src = w_h;   dst = pbH; K = 128; N = 256; tk = b & 3;  tn = b >> 2; }
    else if (b < 48)  { b -= 32;  src = w_out; dst = pbO; K = 128; N = 128; tk = b & 3;  tn = b >> 2; }
    else if (b < 112) { b -= 48;  src = w1;    dst = pb1; K = 128; N = 512; tk = b & 3;  tn = b >> 2; }
    else              { b -= 112; src = w2;    dst = pb2; K = 512; N = 128; tk = b & 15; tn = b >> 4; }
    int k0 = tk * 32, n0 = tn * 32;
    int lx = threadIdx.x & 31, ly = threadIdx.x >> 5;
    #pragma unroll
    for (int j = 0; j < 32; j += 8)
        t[ly + j][lx] = src[(size_t)(k0 + ly + j) * N + n0 + lx];
    __syncthreads();
    #pragma unroll
    for (int j = 0; j < 32; j += 8)
        dst[(size_t)(n0 + ly + j) * K + k0 + lx] = __float2bfloat16(t[lx][ly + j]);
}

// ---------------- cond GEMMs ------------------------------------------------------
__global__ __launch_bounds__(256) void k_cond(const float* __restrict__ cond,
                                              const float* __restrict__ w_mix,
                                              const float* __restrict__ b_mix,
                                              const float* __restrict__ w_mlp,
                                              const float* __restrict__ b_mlp) {
    __shared__ float cs[Aa];
    int g = blockIdx.x;
    int which = blockIdx.y;
    const float* w = which ? w_mlp : w_mix;
    const float* b = which ? b_mlp : b_mix;
    float* outp = which ? g_sb_mlp : g_sb_mix;
    int t = threadIdx.x;
    if (t < Aa) cs[t] = cond[g * Aa + t];
    __syncthreads();
    float acc = b[t];
    #pragma unroll 8
    for (int k = 0; k < Aa; k++) acc = fmaf(cs[k], w[k * F2 + t], acc);
    outp[g * F2 + t] = acc;
}

// ============== node kernel 1 (HMMA, 128-row tile, 2 CTA/SM, cp.async W) ===========
#define N1STR 272
#define N1_OFF_XM 0
#define N1_OFF_W  34816
#define SM_NODE1  104448

__global__ __launch_bounds__(512, 2) void k_node1(const float* __restrict__ input,
                                                  const int* __restrict__ batch,
                                                  const float* __restrict__ b_h) {
    extern __shared__ __align__(16) char smem_raw[];
    const uint32_t smemU = (uint32_t)__cvta_generic_to_shared(smem_raw);
    const int tid = threadIdx.x;
    const int warp = tid >> 5, lane = tid & 31;
    const int nb = blockIdx.x * NTILE;
    char* xm = smem_raw + N1_OFF_XM;

    const uint32_t a4 = ((lane & 7) + ((lane >> 3) & 1) * 8) * N1STR + ((lane >> 4) & 1) * 16;
    const uint32_t b4 = ((lane & 7) + ((lane >> 4) & 1) * 8) * N1STR + ((lane >> 3) & 1) * 16;

    for (int i = tid; i < 256 * 16; i += 512) {
        int n = i >> 4, k16 = i & 15;
        cp16(smemU + N1_OFF_W + n * N1STR + k16 * 16, pbH + n * 128 + k16 * 8);
    }
    CP_COMMIT();

    #pragma unroll
    for (int q = 0; q < 8; q++) {
        int r = warp * 8 + q;
        int n = nb + r;
        int nc = n < Nn ? n : Nn - 1;
        float4 x = ((const float4*)(input + (size_t)nc * Ff))[lane];
        float s  = x.x + x.y + x.z + x.w;
        float ss = fmaf(x.x, x.x, fmaf(x.y, x.y, fmaf(x.z, x.z, x.w * x.w)));
        #pragma unroll
        for (int o = 16; o > 0; o >>= 1) {
            s  += __shfl_xor_sync(0xffffffffu, s, o);
            ss += __shfl_xor_sync(0xffffffffu, ss, o);
        }
        float mu = s * (1.f / Ff);
        float rstd = rsqrtf(ss * (1.f / Ff) - mu * mu + 1e-5f);
        int bix = batch[nc];
        const float* sb = g_sb_mix + bix * F2;
        float4 sc = *((const float4*)(sb + lane * 4));
        float4 sh = *((const float4*)(sb + Ff + lane * 4));
        float o0 = (x.x - mu) * rstd * (1.f + sc.x) + sh.x;
        float o1 = (x.y - mu) * rstd * (1.f + sc.y) + sh.y;
        float o2 = (x.z - mu) * rstd * (1.f + sc.z) + sh.z;
        float o3 = (x.w - mu) * rstd * (1.f + sc.w) + sh.w;
        *(uint32_t*)(xm + r * N1STR + lane * 8)     = pack_bf16(o0, o1);
        *(uint32_t*)(xm + r * N1STR + lane * 8 + 4) = pack_bf16(o2, o3);
    }
    CP_WAIT(0);
    __syncthreads();

    const int wr = warp & 7, wq = warp >> 3;
    const int row0 = wr * 16 + (lane >> 2);
    const int na = nb + row0, nbr = na + 8;
    const uint32_t aBase = smemU + N1_OFF_XM + wr * 16 * N1STR + a4;
    const int tg = lane & 3;

    #pragma unroll
    for (int npass = 0; npass < 2; npass++) {
        float d[8][4];
        #pragma unroll
        for (int i = 0; i < 8; i++) { d[i][0]=0.f; d[i][1]=0.f; d[i][2]=0.f; d[i][3]=0.f; }
        #pragma unroll
        for (int ks = 0; ks < 8; ks++) {
            uint32_t a0, a1, a2, a3;
            ldsm_x4(a0, a1, a2, a3, aBase + ks * 32);
            #pragma unroll
            for (int np = 0; np < 4; np++) {
                int n0 = npass * 128 + wq * 64 + np * 16;
                uint32_t b0, b1, b2, b3;
                ldsm_x4(b0, b1, b2, b3, smemU + N1_OFF_W + n0 * N1STR + b4 + ks * 32);
                mma_bf16(d[2 * np],     a0, a1, a2, a3, b0, b1);
                mma_bf16(d[2 * np + 1], a0, a1, a2, a3, b2, b3);
            }
        }
        __nv_bfloat16* gout = (npass == 0) ? g_hsrcB : g_hdstB;
        #pragma unroll
        for (int nb2 = 0; nb2 < 8; nb2++) {
            int c = npass * 128 + wq * 64 + nb2 * 8 + 2 * tg;
            float bb0 = __ldg(b_h + c), bb1 = __ldg(b_h + c + 1);
            int c2 = c - npass * 128;
            if (na < Nn)
                *(uint32_t*)(gout + (size_t)na * Ff + c2) = pack_bf16(d[nb2][0]+bb0, d[nb2][1]+bb1);
            if (nbr < Nn)
                *(uint32_t*)(gout + (size_t)nbr * Ff + c2) = pack_bf16(d[nb2][2]+bb0, d[nb2][3]+bb1);
        }
    }
}

// ========== bf16 edge kernel — 128-edge tile, 4(Mx32) x 4(N) warp grid =============
#define STRA 144
#define STRB 272
#define OFF_WAT  0            // 128*144 = 18432
#define OFF_WCT  18432        // 224*272 -> ends 79360
#define OFF_AN   79360        // 128*144 -> ends 97792
#define OFF_M    97792        // 128*272 -> ends 132608
#define OFF_WEXP 132608       // 128*9*4 -> 137216
#define OFF_SRC  137216       // 512
#define OFF_GE   137728
#define OFF_BE   137984
#define OFF_BD   138240
#define SMEDGE   138496       // 1 CTA/SM

__global__ __launch_bounds__(512, 1) void k_edge(const float* __restrict__ ain,
                                                 const int* __restrict__ edges,
                                                 const float* __restrict__ w_a,
                                                 const float* __restrict__ w_vatt,
                                                 const float* __restrict__ w_edge,
                                                 const float* __restrict__ gain_e,
                                                 const float* __restrict__ bias_e,
                                                 const float* __restrict__ b_edge,
                                                 float* __restrict__ aout) {
    extern __shared__ __align__(16) char smem_raw[];
    const uint32_t smemU = (uint32_t)__cvta_generic_to_shared(smem_raw);
    const int tid = threadIdx.x;
    const int warp = tid >> 5, lane = tid & 31;
    const int g = lane >> 2, tg = lane & 3;
    const int wr = warp & 3;       // M group: 32 rows
    const int wq = warp >> 2;      // N group

    float* wexp_s = (float*)(smem_raw + OFF_WEXP);
    int*   src_s  = (int*)(smem_raw + OFF_SRC);
    float* ge_s   = (float*)(smem_raw + OFF_GE);
    float* be_s   = (float*)(smem_raw + OFF_BE);
    float* bd_s   = (float*)(smem_raw + OFF_BD);

    const uint32_t a4A = ((lane & 7) + ((lane >> 3) & 1) * 8) * STRA + ((lane >> 4) & 1) * 16;
    const uint32_t b4A = ((lane & 7) + ((lane >> 4) & 1) * 8) * STRA + ((lane >> 3) & 1) * 16;
    const uint32_t a4B = ((lane & 7) + ((lane >> 3) & 1) * 8) * STRB + ((lane >> 4) & 1) * 16;
    const uint32_t b4B = ((lane & 7) + ((lane >> 4) & 1) * 8) * STRB + ((lane >> 3) & 1) * 16;
    const uint32_t x2B = (lane & 7) * STRB + ((lane >> 3) & 1) * 16;

    for (int i = tid; i < 128 * 64; i += 512) {
        int n = i & 127, k = i >> 7;
        *(__nv_bfloat16*)(smem_raw + OFF_WAT + n * STRA + k * 2) =
            __float2bfloat16(w_a[k * Ff + n]);
    }
    for (int i = tid; i < 224 * 128; i += 512) {
        int n = i % 224, k = i / 224;
        float v = 0.f;
        if (n < 136)               v = w_vatt[k * 136 + n];
        else if (n < 200)          v = w_edge[k * EFe + (n - 136)];
        *(__nv_bfloat16*)(smem_raw + OFF_WCT + n * STRB + k * 2) = __float2bfloat16(v);
    }
    if (tid < EFe) { ge_s[tid] = gain_e[tid]; be_s[tid] = bias_e[tid]; bd_s[tid] = b_edge[tid]; }
    __syncthreads();

    for (int tile = blockIdx.x; tile < NTILES; tile += gridDim.x) {
        const int e0 = tile * ETILE;

        if (tid < ETILE) src_s[tid] = edges[e0 + tid];

        // ---- LN(a) -> an (bf16). Each warp: 8 rows ----
        #pragma unroll
        for (int q = 0; q < 8; q++) {
            int r = warp * 8 + q;
            float2 x = *(const float2*)(ain + (size_t)(e0 + r) * EFe + 2 * lane);
            float s = x.x + x.y;
            float ss = fmaf(x.x, x.x, x.y * x.y);
            #pragma unroll
            for (int o = 16; o > 0; o >>= 1) {
                s  += __shfl_xor_sync(0xffffffffu, s, o);
                ss += __shfl_xor_sync(0xffffffffu, ss, o);
            }
            float mu = s * (1.f / EFe);
            float rstd = rsqrtf(ss * (1.f / EFe) - mu * mu + 1e-5f);
            float v0 = (x.x - mu) * rstd * ge_s[2 * lane]     + be_s[2 * lane];
            float v1 = (x.y - mu) * rstd * ge_s[2 * lane + 1] + be_s[2 * lane + 1];
            *(uint32_t*)(smem_raw + OFF_AN + r * STRA + lane * 4) = pack_bf16(v0, v1);
        }

        // ---- hsum (bf16 gathers) -> m_s ----
        #pragma unroll
        for (int q = 0; q < 8; q++) {
            int r = warp * 8 + q;
            int sr = __ldg(edges + e0 + r);
            int dr = __ldg(edges + Ee + e0 + r);
            uint2 hs = *(const uint2*)(g_hsrcB + (size_t)sr * Ff + lane * 4);
            uint2 hd = *(const uint2*)(g_hdstB + (size_t)dr * Ff + lane * 4);
            float2 s0f = unpack_bf16(hs.x), s1f = unpack_bf16(hs.y);
            float2 d0f = unpack_bf16(hd.x), d1f = unpack_bf16(hd.y);
            uint2 p;
            p.x = pack_bf16(s0f.x + d0f.x, s0f.y + d0f.y);
            p.y = pack_bf16(s1f.x + d1f.x, s1f.y + d1f.y);
            *(uint2*)(smem_raw + OFF_M + r * STRB + lane * 8) = p;
        }
        __syncthreads();   // sync1

        // ---- GEMM1: D1[128,128] = an @ w_a; warp: 32 rows x 32 cols ----
        float d1[2][4][4];
        #pragma unroll
        for (int m = 0; m < 2; m++)
            #pragma unroll
            for (int i = 0; i < 4; i++) { d1[m][i][0]=0.f; d1[m][i][1]=0.f; d1[m][i][2]=0.f; d1[m][i][3]=0.f; }
        {
            const uint32_t aB0 = smemU + OFF_AN + (wr * 32) * STRA + a4A;
            const uint32_t aB1 = aB0 + 16 * STRA;
            #pragma unroll
            for (int ks = 0; ks < 4; ks++) {
                uint32_t p0, p1, p2, p3, q0, q1, q2, q3;
                ldsm_x4(p0, p1, p2, p3, aB0 + ks * 32);
                ldsm_x4(q0, q1, q2, q3, aB1 + ks * 32);
                #pragma unroll
                for (int np = 0; np < 2; np++) {
                    int n0 = wq * 32 + np * 16;
                    uint32_t b0, b1, b2, b3;
                    ldsm_x4(b0, b1, b2, b3, smemU + OFF_WAT + n0 * STRA + b4A + ks * 32);
                    mma_bf16(d1[0][2 * np],     p0, p1, p2, p3, b0, b1);
                    mma_bf16(d1[0][2 * np + 1], p0, p1, p2, p3, b2, b3);
                    mma_bf16(d1[1][2 * np],     q0, q1, q2, q3, b0, b1);
                    mma_bf16(d1[1][2 * np + 1], q0, q1, q2, q3, b2, b3);
                }
            }
        }

        // ---- epilogue 1: m = silu(D1 + hsum) in place ----
        #pragma unroll
        for (int m = 0; m < 2; m++) {
            int r0 = wr * 32 + m * 16 + g, r1 = r0 + 8;
            #pragma unroll
            for (int nb = 0; nb < 4; nb++) {
                int col = wq * 32 + nb * 8 + 2 * tg;
                float2 h0 = unpack_bf16(*(const uint32_t*)(smem_raw + OFF_M + r0 * STRB + col * 2));
                float2 h1 = unpack_bf16(*(const uint32_t*)(smem_raw + OFF_M + r1 * STRB + col * 2));
                *(uint32_t*)(smem_raw + OFF_M + r0 * STRB + col * 2) =
                    pack_bf16(siluf(d1[m][nb][0] + h0.x), siluf(d1[m][nb][1] + h0.y));
                *(uint32_t*)(smem_raw + OFF_M + r1 * STRB + col * 2) =
                    pack_bf16(siluf(d1[m][nb][2] + h1.x), siluf(d1[m][nb][3] + h1.y));
            }
        }
        __syncthreads();   // sync2: m ready

        // ---- GEMM2: D2[128,224] = m @ wc; warp: 32 rows x 56 cols ----
        float d2[2][7][4];
        #pragma unroll
        for (int m = 0; m < 2; m++)
            #pragma unroll
            for (int i = 0; i < 7; i++) { d2[m][i][0]=0.f; d2[m][i][1]=0.f; d2[m][i][2]=0.f; d2[m][i][3]=0.f; }
        {
            const uint32_t aB0 = smemU + OFF_M + (wr * 32) * STRB + a4B;
            const uint32_t aB1 = aB0 + 16 * STRB;
            #pragma unroll
            for (int ks = 0; ks < 8; ks++) {
                uint32_t p0, p1, p2, p3, q0, q1, q2, q3;
                ldsm_x4(p0, p1, p2, p3, aB0 + ks * 32);
                ldsm_x4(q0, q1, q2, q3, aB1 + ks * 32);
                #pragma unroll
                for (int np = 0; np < 3; np++) {
                    int n0 = wq * 56 + np * 16;
                    uint32_t b0, b1, b2, b3;
                    ldsm_x4(b0, b1, b2, b3, smemU + OFF_WCT + n0 * STRB + b4B + ks * 32);
                    mma_bf16(d2[0][2 * np],     p0, p1, p2, p3, b0, b1);
                    mma_bf16(d2[0][2 * np + 1], p0, p1, p2, p3, b2, b3);
                    mma_bf16(d2[1][2 * np],     q0, q1, q2, q3, b0, b1);
                    mma_bf16(d2[1][2 * np + 1], q0, q1, q2, q3, b2, b3);
                }
                {
                    int n0 = wq * 56 + 48;
                    uint32_t b0, b1;
                    ldsm_x2(b0, b1, smemU + OFF_WCT + n0 * STRB + x2B + ks * 32);
                    mma_bf16(d2[0][6], p0, p1, p2, p3, b0, b1);
                    mma_bf16(d2[1][6], q0, q1, q2, q3, b0, b1);
                }
            }
        }

        // head logits: cols 128..135 = (wq==2, nb==2)
        if (wq == 2) {
            int h = 2 * tg;
            #pragma unroll
            for (int m = 0; m < 2; m++) {
                int r0 = wr * 32 + m * 16 + g, r1 = r0 + 8;
                int s0 = src_s[r0], s1 = src_s[r1];
                float e00 = __expf(d2[m][2][0]);
                float e01 = __expf(d2[m][2][1]);
                float e10 = __expf(d2[m][2][2]);
                float e11 = __expf(d2[m][2][3]);
                wexp_s[r0 * 9 + h]     = e00;
                wexp_s[r0 * 9 + h + 1] = e01;
                wexp_s[r1 * 9 + h]     = e10;
                wexp_s[r1 * 9 + h + 1] = e11;
                float* p0 = g_wsum + (size_t)s0 * Hh + h;
                float* p1 = g_wsum + (size_t)s1 * Hh + h;
                asm volatile("red.global.add.f32 [%0], %1;" :: "l"(p0),     "f"(e00) : "memory");
                asm volatile("red.global.add.f32 [%0], %1;" :: "l"(p0 + 1), "f"(e01) : "memory");
                asm volatile("red.global.add.f32 [%0], %1;" :: "l"(p1),     "f"(e10) : "memory");
                asm volatile("red.global.add.f32 [%0], %1;" :: "l"(p1 + 1), "f"(e11) : "memory");
            }
        }
        __syncthreads();   // sync3

        // ---- v-stage: wexp*v -> m_s; da -> an buffer ----
        #pragma unroll
        for (int m = 0; m < 2; m++) {
            int r0 = wr * 32 + m * 16 + g, r1 = r0 + 8;
            #pragma unroll
            for (int nb = 0; nb < 7; nb++) {
                int col = wq * 56 + nb * 8 + 2 * tg;
                if (col < Ff) {
                    int h = col >> 4;
                    float w0 = wexp_s[r0 * 9 + h];
                    float w1 = wexp_s[r1 * 9 + h];
                    *(uint32_t*)(smem_raw + OFF_M + r0 * STRB + col * 2) =
                        pack_bf16(d2[m][nb][0] * w0, d2[m][nb][1] * w0);
                    *(uint32_t*)(smem_raw + OFF_M + r1 * STRB + col * 2) =
                        pack_bf16(d2[m][nb][2] * w1, d2[m][nb][3] * w1);
                } else if (col >= 136 && col < 200) {
                    int k2 = col - 136;
                    *(uint32_t*)(smem_raw + OFF_AN + r0 * STRA + k2 * 2) =
                        pack_bf16(d2[m][nb][0], d2[m][nb][1]);
                    *(uint32_t*)(smem_raw + OFF_AN + r1 * STRA + k2 * 2) =
                        pack_bf16(d2[m][nb][2], d2[m][nb][3]);
                }
            }
        }
        __syncthreads();   // sync4

        // ---- cooperative coalesced epilogues ----
        #pragma unroll
        for (int q = 0; q < 8; q++) {
            int r = warp * 8 + q;
            int sr = src_s[r];
            uint2 p = *(const uint2*)(smem_raw + OFF_M + r * STRB + lane * 8);
            float2 v01 = unpack_bf16(p.x);
            float2 v23 = unpack_bf16(p.y);
            float* ob = g_o + (size_t)sr * Ff + lane * 4;
            asm volatile("red.global.add.v4.f32 [%0], {%1, %2, %3, %4};"
                         :: "l"(ob), "f"(v01.x), "f"(v01.y), "f"(v23.x), "f"(v23.y)
                         : "memory");
            float2 da = unpack_bf16(*(const uint32_t*)(smem_raw + OFF_AN + r * STRA + lane * 4));
            float2 av = *(const float2*)(ain + (size_t)(e0 + r) * EFe + 2 * lane);
            float2 ro;
            ro.x = av.x + da.x + bd_s[2 * lane];
            ro.y = av.y + da.y + bd_s[2 * lane + 1];
            *(float2*)(aout + (size_t)(e0 + r) * EFe + 2 * lane) = ro;
        }
        __syncthreads();   // sync5
    }
}

// ============== fused node kernel 2 + MLP (double-buffered cp.async weights) =======
#define N2STR 272
#define OFF2_W  0
#define OFF2_W2 34816
#define OFF2_XN 69632
#define OFF2_T  104448
#define OFF2_HM 139264
#define SM_N2M  208896

__global__ __launch_bounds__(512) void k_node2mlp(const float* __restrict__ input,
                                                  const int* __restrict__ batch,
                                                  const float* __restrict__ b_out,
                                                  const float* __restrict__ b1,
                                                  const float* __restrict__ b2,
                                                  float* __restrict__ hout) {
    extern __shared__ __align__(16) char smem_raw[];
    const uint32_t smemU = (uint32_t)__cvta_generic_to_shared(smem_raw);
    const int tid = threadIdx.x;
    const int warp = tid >> 5, lane = tid & 31;
    const int g = lane >> 2, tg = lane & 3;
    const int wr = warp & 7, wq = warp >> 3;
    const int nb = blockIdx.x * NTILE;
    char* xnb  = smem_raw + OFF2_XN;
    char* tb   = smem_raw + OFF2_T;
    float* hm_s = (float*)(smem_raw + OFF2_HM);

    const uint32_t a4 = ((lane & 7) + ((lane >> 3) & 1) * 8) * N2STR + ((lane >> 4) & 1) * 16;
    const uint32_t b4 = ((lane & 7) + ((lane >> 4) & 1) * 8) * N2STR + ((lane >> 3) & 1) * 16;
    const uint32_t aRow = wr * 16 * N2STR + a4;

    for (int i = tid; i < 2048; i += 512) {
        int n = i >> 4, k16 = i & 15;
        cp16(smemU + OFF2_W + n * N2STR + k16 * 16, pbO + n * 128 + k16 * 8);
    }
    CP_COMMIT();
    for (int i = tid; i < 2048; i += 512) {
        int n = i >> 4, k16 = i & 15;
        cp16(smemU + OFF2_W2 + n * N2STR + k16 * 16, pb1 + n * 128 + k16 * 8);
    }
    CP_COMMIT();

    for (int i = tid; i < NTILE * 32; i += 512) {
        int r = i >> 5, c4 = i & 31;
        int n = nb + r;
        int nc = n < Nn ? n : Nn - 1;
        float4 o4 = ((const float4*)(g_o + (size_t)nc * Ff))[c4];
        int h = c4 >> 2;
        float inv = 1.f / (g_wsum[nc * Hh + h] + 1e-16f);
        *(uint32_t*)(tb + r * N2STR + c4 * 8)     = pack_bf16(o4.x * inv, o4.y * inv);
        *(uint32_t*)(tb + r * N2STR + c4 * 8 + 4) = pack_bf16(o4.z * inv, o4.w * inv);
    }
    CP_WAIT(1);
    __syncthreads();

    const int row0 = wr * 16 + g, row1 = row0 + 8;
    const int na = nb + row0, nb1 = nb + row1;
    const int nca = na < Nn ? na : Nn - 1;
    const int ncb = nb1 < Nn ? nb1 : Nn - 1;

    {
        float d[8][4];
        #pragma unroll
        for (int i = 0; i < 8; i++) { d[i][0]=0.f; d[i][1]=0.f; d[i][2]=0.f; d[i][3]=0.f; }
        #pragma unroll
        for (int ks = 0; ks < 8; ks++) {
            uint32_t a0, a1, a2, a3;
            ldsm_x4(a0, a1, a2, a3, smemU + OFF2_T + aRow + ks * 32);
            #pragma unroll
            for (int np = 0; np < 4; np++) {
                int n0 = wq * 64 + np * 16;
                uint32_t b0, b1, b2, b3;
                ldsm_x4(b0, b1, b2, b3, smemU + OFF2_W + n0 * N2STR + b4 + ks * 32);
                mma_bf16(d[2 * np],     a0, a1, a2, a3, b0, b1);
                mma_bf16(d[2 * np + 1], a0, a1, a2, a3, b2, b3);
            }
        }
        #pragma unroll
        for (int nb2 = 0; nb2 < 8; nb2++) {
            int c = wq * 64 + nb2 * 8 + 2 * tg;
            float2 ia = *(const float2*)(input + (size_t)nca * Ff + c);
            float2 ib = *(const float2*)(input + (size_t)ncb * Ff + c);
            float bb0 = __ldg(b_out + c), bb1 = __ldg(b_out + c + 1);
            hm_s[row0 * 136 + c]     = d[nb2][0] + ia.x + bb0;
            hm_s[row0 * 136 + c + 1] = d[nb2][1] + ia.y + bb1;
            hm_s[row1 * 136 + c]     = d[nb2][2] + ib.x + bb0;
            hm_s[row1 * 136 + c + 1] = d[nb2][3] + ib.y + bb1;
        }
    }
    __syncthreads();

    #pragma unroll
    for (int q = 0; q < 8; q++) {
        int r = warp * 8 + q;
        int n = nb + r;
        int nc = n < Nn ? n : Nn - 1;
        float4 x = ((const float4*)(hm_s + r * 136))[lane];
        float s  = x.x + x.y + x.z + x.w;
        float ss = fmaf(x.x, x.x, fmaf(x.y, x.y, fmaf(x.z, x.z, x.w * x.w)));
        #pragma unroll
        for (int o = 16; o > 0; o >>= 1) {
            s  += __shfl_xor_sync(0xffffffffu, s, o);
            ss += __shfl_xor_sync(0xffffffffu, ss, o);
        }
        float mu = s * (1.f / Ff);
        float rstd = rsqrtf(ss * (1.f / Ff) - mu * mu + 1e-5f);
        int bix = batch[nc];
        const float* sb = g_sb_mlp + bix * F2;
        float4 sc = *((const float4*)(sb + lane * 4));
        float4 sh = *((const float4*)(sb + Ff + lane * 4));
        float o0 = (x.x - mu) * rstd * (1.f + sc.x) + sh.x;
        float o1 = (x.y - mu) * rstd * (1.f + sc.y) + sh.y;
        float o2 = (x.z - mu) * rstd * (1.f + sc.z) + sh.z;
        float o3 = (x.w - mu) * rstd * (1.f + sc.w) + sh.w;
        *(uint32_t*)(xnb + r * N2STR + lane * 8)     = pack_bf16(o0, o1);
        *(uint32_t*)(xnb + r * N2STR + lane * 8 + 4) = pack_bf16(o2, o3);
    }

    float oacc[8][4];
    #pragma unroll
    for (int i = 0; i < 8; i++) { oacc[i][0]=0.f; oacc[i][1]=0.f; oacc[i][2]=0.f; oacc[i][3]=0.f; }

    for (int ch = 0; ch < 4; ch++) {
        __syncthreads();
        for (int i = tid; i < 2048; i += 512) {
            int n = i >> 4, k16 = i & 15;
            cp16(smemU + OFF2_W + n * N2STR + k16 * 16, pb2 + n * 512 + ch * 128 + k16 * 8);
        }
        CP_COMMIT();
        CP_WAIT(1);
        __syncthreads();

        float dt[8][4];
        #pragma unroll
        for (int i = 0; i < 8; i++) { dt[i][0]=0.f; dt[i][1]=0.f; dt[i][2]=0.f; dt[i][3]=0.f; }
        #pragma unroll
        for (int ks = 0; ks < 8; ks++) {
            uint32_t a0, a1, a2, a3;
            ldsm_x4(a0, a1, a2, a3, smemU + OFF2_XN + aRow + ks * 32);
            #pragma unroll
            for (int np = 0; np < 4; np++) {
                int n0 = wq * 64 + np * 16;
                uint32_t b0, b1, b2, b3;
                ldsm_x4(b0, b1, b2, b3, smemU + OFF2_W2 + n0 * N2STR + b4 + ks * 32);
                mma_bf16(dt[2 * np],     a0, a1, a2, a3, b0, b1);
                mma_bf16(dt[2 * np + 1], a0, a1, a2, a3, b2, b3);
            }
        }
        #pragma unroll
        for (int nb2 = 0; nb2 < 8; nb2++) {
            int c = wq * 64 + nb2 * 8 + 2 * tg;
            float b10 = __ldg(b1 + ch * 128 + c), b11 = __ldg(b1 + ch * 128 + c + 1);
            *(uint32_t*)(tb + row0 * N2STR + c * 2) =
                pack_bf16(siluf(dt[nb2][0] + b10), siluf(dt[nb2][1] + b11));
            *(uint32_t*)(tb + row1 * N2STR + c * 2) =
                pack_bf16(siluf(dt[nb2][2] + b10), siluf(dt[nb2][3] + b11));
        }
        __syncthreads();
        if (ch < 3) {
            for (int i = tid; i < 2048; i += 512) {
                int n = i >> 4, k16 = i & 15;
                cp16(smemU + OFF2_W2 + n * N2STR + k16 * 16,
                     pb1 + (size_t)(ch + 1) * 128 * 128 + n * 128 + k16 * 8);
            }
            CP_COMMIT();
            CP_WAIT(1);
        } else {
            CP_WAIT(0);
        }
        __syncthreads();

        #pragma unroll
        for (int ks = 0; ks < 8; ks++) {
            uint32_t a0, a1, a2, a3;
            ldsm_x4(a0, a1, a2, a3, smemU + OFF2_T + aRow + ks * 32);
            #pragma unroll
            for (int np = 0; np < 4; np++) {
                int n0 = wq * 64 + np * 16;
                uint32_t b0, b1, b2, b3;
                ldsm_x4(b0, b1, b2, b3, smemU + OFF2_W + n0 * N2STR + b4 + ks * 32);
                mma_bf16(oacc[2 * np],     a0, a1, a2, a3, b0, b1);
                mma_bf16(oacc[2 * np + 1], a0, a1, a2, a3, b2, b3);
            }
        }
    }

    #pragma unroll
    for (int nb2 = 0; nb2 < 8; nb2++) {
        int c = wq * 64 + nb2 * 8 + 2 * tg;
        float b20 = __ldg(b2 + c), b21 = __ldg(b2 + c + 1);
        if (na < Nn) {
            float2 v = {oacc[nb2][0] + hm_s[row0 * 136 + c]     + b20,
                        oacc[nb2][1] + hm_s[row0 * 136 + c + 1] + b21};
            *(float2*)(hout + (size_t)na * Ff + c) = v;
        }
        if (nb1 < Nn) {
            float2 v = {oacc[nb2][2] + hm_s[row1 * 136 + c]     + b20,
                        oacc[nb2][3] + hm_s[row1 * 136 + c + 1] + b21};
            *(float2*)(hout + (size_t)nb1 * Ff + c) = v;
        }
    }
}

// ---------------- launcher ---------------------------------------------------------
extern "C" void kernel_launch(void* const* d_in, const int* in_sizes, int n_in,
                              void* d_out, int out_size) {
    const float* input     = (const float*)d_in[0];
    const float* cond      = (const float*)d_in[1];
    const float* a         = (const float*)d_in[2];
    const int*   batch     = (const int*)d_in[3];
    const int*   edges     = (const int*)d_in[4];
    const float* w_ada_mix = (const float*)d_in[5];
    const float* b_ada_mix = (const float*)d_in[6];
    const float* w_h       = (const float*)d_in[7];
    const float* b_h       = (const float*)d_in[8];
    const float* w_a       = (const float*)d_in[9];
    const float* w_vatt    = (const float*)d_in[10];
    const float* w_out     = (const float*)d_in[11];
    const float* b_out     = (const float*)d_in[12];
    const float* g_edge_p  = (const float*)d_in[13];
    const float* be_edge_p = (const float*)d_in[14];
    const float* w_edge    = (const float*)d_in[15];
    const float* b_edge    = (const float*)d_in[16];
    const float* w_ada_mlp = (const float*)d_in[17];
    const float* b_ada_mlp = (const float*)d_in[18];
    const float* w1        = (const float*)d_in[19];
    const float* b1        = (const float*)d_in[20];
    const float* w2        = (const float*)d_in[21];
    const float* b2        = (const float*)d_in[22];

    float* hout = (float*)d_out;                       // h: [N, F]
    float* aout = (float*)d_out + (size_t)Nn * Ff;     // a_out: [E, EF]

    cudaFuncSetAttribute(k_node1,    cudaFuncAttributeMaxDynamicSharedMemorySize, SM_NODE1);
    cudaFuncSetAttribute(k_edge,     cudaFuncAttributeMaxDynamicSharedMemorySize, SMEDGE);
    cudaFuncSetAttribute(k_node2mlp, cudaFuncAttributeMaxDynamicSharedMemorySize, SM_N2M);

    const int NT = (Nn + NTILE - 1) / NTILE;  // 157

    k_init<<<(Nn * Ff + 255) / 256, 256>>>();
    k_prep<<<176, 256>>>(w_h, w_out, w1, w2);
    k_cond<<<dim3(Gg, 2), 256>>>(cond, w_ada_mix, b_ada_mix, w_ada_mlp, b_ada_mlp);
    k_node1<<<NT, 512, SM_NODE1>>>(input, batch, b_h);
    k_edge<<<148, 512, SMEDGE>>>(a, edges, w_a, w_vatt, w_edge,
                                 g_edge_p, be_edge_p, b_edge, aout);
    k_node2mlp<<<NT, 512, SM_N2M>>>(input, batch, b_out, b1, b2, hout);
}

// round 16
// speedup vs baseline: 1.0511x; 1.0511x over previous
#include <cuda_runtime.h>
#include <cuda_bf16.h>
#include <cstdint>
#include <cstddef>

#define Nn 20000
#define Ee 320000
#define Ff 128
#define Hh 8
#define EFe 64
#define Aa 128
#define Gg 32
#define F2 256
#define NTILE 128
#define ETILE 64
#define NTILES (Ee / ETILE)

// ---------------- scratch (device globals; no allocations allowed) ----------------
__device__ float g_sb_mix[Gg * F2];
__device__ float g_sb_mlp[Gg * F2];
__device__ __nv_bfloat16 g_hsrcB[(size_t)Nn * Ff];
__device__ __nv_bfloat16 g_hdstB[(size_t)Nn * Ff];
__device__ float g_wsum[Nn * Hh];
__device__ float g_o[(size_t)Nn * Ff];
// prepacked bf16 transposed weights
__device__ __nv_bfloat16 pbH[256 * 128];
__device__ __nv_bfloat16 pbO[128 * 128];
__device__ __nv_bfloat16 pb1[512 * 128];
__device__ __nv_bfloat16 pb2[128 * 512];

__device__ __forceinline__ float siluf(float x) { return x / (1.f + __expf(-x)); }

__device__ __forceinline__ void mma_bf16(float* d, uint32_t a0, uint32_t a1,
                                         uint32_t a2, uint32_t a3,
                                         uint32_t b0, uint32_t b1) {
    asm volatile(
        "mma.sync.aligned.m16n8k16.row.col.f32.bf16.bf16.f32 "
        "{%0,%1,%2,%3}, {%4,%5,%6,%7}, {%8,%9}, {%0,%1,%2,%3};"
        : "+f"(d[0]), "+f"(d[1]), "+f"(d[2]), "+f"(d[3])
        : "r"(a0), "r"(a1), "r"(a2), "r"(a3), "r"(b0), "r"(b1));
}

__device__ __forceinline__ void ldsm_x4(uint32_t& r0, uint32_t& r1,
                                        uint32_t& r2, uint32_t& r3, uint32_t addr) {
    asm volatile("ldmatrix.sync.aligned.m8n8.x4.shared.b16 {%0,%1,%2,%3}, [%4];"
                 : "=r"(r0), "=r"(r1), "=r"(r2), "=r"(r3) : "r"(addr));
}
__device__ __forceinline__ void ldsm_x2(uint32_t& r0, uint32_t& r1, uint32_t addr) {
    asm volatile("ldmatrix.sync.aligned.m8n8.x2.shared.b16 {%0,%1}, [%2];"
                 : "=r"(r0), "=r"(r1) : "r"(addr));
}

__device__ __forceinline__ void cp16(uint32_t dst, const void* src) {
    asm volatile("cp.async.cg.shared.global [%0], [%1], 16;" :: "r"(dst), "l"(src));
}
#define CP_COMMIT() asm volatile("cp.async.commit_group;" ::: "memory")
#define CP_WAIT(N)  asm volatile("cp.async.wait_group %0;" :: "n"(N) : "memory")

__device__ __forceinline__ uint32_t pack_bf16(float a, float b) {
    __nv_bfloat162 p = __floats2bfloat162_rn(a, b);
    return *(uint32_t*)&p;
}
__device__ __forceinline__ float2 unpack_bf16(uint32_t u) {
    __nv_bfloat162 p = *(__nv_bfloat162*)&u;
    return make_float2(__bfloat162float(p.x), __bfloat162float(p.y));
}

// ---------------- init: zero accumulators ----------------------------------------
__global__ void k_init() {
    int i = blockIdx.x * 256 + threadIdx.x;
    if (i < Nn * Ff) g_o[i] = 0.f;
    if (i < Nn * Hh) g_wsum[i] = 0.f;
}

// ---------------- k_prep: tiled-transpose weights into bf16 [n][k] ----------------
__global__ __launch_bounds__(256) void k_prep(const float* __restrict__ w_h,
                                              const float* __restrict__ w_out,
                                              const float* __restrict__ w1,
                                              const float* __restrict__ w2) {
    __shared__ float t[32][33];
    int b = blockIdx.x;
    const float* src; __nv_bfloat16* dst; int K, N, tk, tn;
    if (b < 32)       { src = w_h;   dst = pbH; K = 128; N = 256; tk = b & 3;  tn = b >> 2; }
    else if (b < 48)  { b -= 32;  src = w_out; dst = pbO; K = 128; N = 128; tk = b & 3;  tn = b >> 2; }
    else if (b < 112) { b -= 48;  src = w1;    dst = pb1; K = 128; N = 512; tk = b & 3;  tn = b >> 2; }
    else              { b -= 112; src = w2;    dst = pb2; K = 512; N = 128; tk = b & 15; tn = b >> 4; }
    int k0 = tk * 32, n0 = tn * 32;
    int lx = threadIdx.x & 31, ly = threadIdx.x >> 5;
    #pragma unroll
    for (int j = 0; j < 32; j += 8)
        t[ly + j][lx] = src[(size_t)(k0 + ly + j) * N + n0 + lx];
    __syncthreads();
    #pragma unroll
    for (int j = 0; j < 32; j += 8)
        dst[(size_t)(n0 + ly + j) * K + k0 + lx] = __float2bfloat16(t[lx][ly + j]);
}

// ---------------- cond GEMMs ------------------------------------------------------
__global__ __launch_bounds__(256) void k_cond(const float* __restrict__ cond,
                                              const float* __restrict__ w_mix,
                                              const float* __restrict__ b_mix,
                                              const float* __restrict__ w_mlp,
                                              const float* __restrict__ b_mlp) {
    __shared__ float cs[Aa];
    int g = blockIdx.x;
    int which = blockIdx.y;
    const float* w = which ? w_mlp : w_mix;
    const float* b = which ? b_mlp : b_mix;
    float* outp = which ? g_sb_mlp : g_sb_mix;
    int t = threadIdx.x;
    if (t < Aa) cs[t] = cond[g * Aa + t];
    __syncthreads();
    float acc = b[t];
    #pragma unroll 8
    for (int k = 0; k < Aa; k++) acc = fmaf(cs[k], w[k * F2 + t], acc);
    outp[g * F2 + t] = acc;
}

// ============== node kernel 1 (HMMA, 128-row tile, 2 CTA/SM, cp.async W) ===========
#define N1STR 272
#define N1_OFF_XM 0
#define N1_OFF_W  34816
#define SM_NODE1  104448

__global__ __launch_bounds__(512, 2) void k_node1(const float* __restrict__ input,
                                                  const int* __restrict__ batch,
                                                  const float* __restrict__ b_h) {
    extern __shared__ __align__(16) char smem_raw[];
    const uint32_t smemU = (uint32_t)__cvta_generic_to_shared(smem_raw);
    const int tid = threadIdx.x;
    const int warp = tid >> 5, lane = tid & 31;
    const int nb = blockIdx.x * NTILE;
    char* xm = smem_raw + N1_OFF_XM;

    const uint32_t a4 = ((lane & 7) + ((lane >> 3) & 1) * 8) * N1STR + ((lane >> 4) & 1) * 16;
    const uint32_t b4 = ((lane & 7) + ((lane >> 4) & 1) * 8) * N1STR + ((lane >> 3) & 1) * 16;

    for (int i = tid; i < 256 * 16; i += 512) {
        int n = i >> 4, k16 = i & 15;
        cp16(smemU + N1_OFF_W + n * N1STR + k16 * 16, pbH + n * 128 + k16 * 8);
    }
    CP_COMMIT();

    #pragma unroll
    for (int q = 0; q < 8; q++) {
        int r = warp * 8 + q;
        int n = nb + r;
        int nc = n < Nn ? n : Nn - 1;
        float4 x = ((const float4*)(input + (size_t)nc * Ff))[lane];
        float s  = x.x + x.y + x.z + x.w;
        float ss = fmaf(x.x, x.x, fmaf(x.y, x.y, fmaf(x.z, x.z, x.w * x.w)));
        #pragma unroll
        for (int o = 16; o > 0; o >>= 1) {
            s  += __shfl_xor_sync(0xffffffffu, s, o);
            ss += __shfl_xor_sync(0xffffffffu, ss, o);
        }
        float mu = s * (1.f / Ff);
        float rstd = rsqrtf(ss * (1.f / Ff) - mu * mu + 1e-5f);
        int bix = batch[nc];
        const float* sb = g_sb_mix + bix * F2;
        float4 sc = *((const float4*)(sb + lane * 4));
        float4 sh = *((const float4*)(sb + Ff + lane * 4));
        float o0 = (x.x - mu) * rstd * (1.f + sc.x) + sh.x;
        float o1 = (x.y - mu) * rstd * (1.f + sc.y) + sh.y;
        float o2 = (x.z - mu) * rstd * (1.f + sc.z) + sh.z;
        float o3 = (x.w - mu) * rstd * (1.f + sc.w) + sh.w;
        *(uint32_t*)(xm + r * N1STR + lane * 8)     = pack_bf16(o0, o1);
        *(uint32_t*)(xm + r * N1STR + lane * 8 + 4) = pack_bf16(o2, o3);
    }
    CP_WAIT(0);
    __syncthreads();

    const int wr = warp & 7, wq = warp >> 3;
    const int row0 = wr * 16 + (lane >> 2);
    const int na = nb + row0, nbr = na + 8;
    const uint32_t aBase = smemU + N1_OFF_XM + wr * 16 * N1STR + a4;
    const int tg = lane & 3;

    #pragma unroll
    for (int npass = 0; npass < 2; npass++) {
        float d[8][4];
        #pragma unroll
        for (int i = 0; i < 8; i++) { d[i][0]=0.f; d[i][1]=0.f; d[i][2]=0.f; d[i][3]=0.f; }
        #pragma unroll
        for (int ks = 0; ks < 8; ks++) {
            uint32_t a0, a1, a2, a3;
            ldsm_x4(a0, a1, a2, a3, aBase + ks * 32);
            #pragma unroll
            for (int np = 0; np < 4; np++) {
                int n0 = npass * 128 + wq * 64 + np * 16;
                uint32_t b0, b1, b2, b3;
                ldsm_x4(b0, b1, b2, b3, smemU + N1_OFF_W + n0 * N1STR + b4 + ks * 32);
                mma_bf16(d[2 * np],     a0, a1, a2, a3, b0, b1);
                mma_bf16(d[2 * np + 1], a0, a1, a2, a3, b2, b3);
            }
        }
        __nv_bfloat16* gout = (npass == 0) ? g_hsrcB : g_hdstB;
        #pragma unroll
        for (int nb2 = 0; nb2 < 8; nb2++) {
            int c = npass * 128 + wq * 64 + nb2 * 8 + 2 * tg;
            float bb0 = __ldg(b_h + c), bb1 = __ldg(b_h + c + 1);
            int c2 = c - npass * 128;
            if (na < Nn)
                *(uint32_t*)(gout + (size_t)na * Ff + c2) = pack_bf16(d[nb2][0]+bb0, d[nb2][1]+bb1);
            if (nbr < Nn)
                *(uint32_t*)(gout + (size_t)nbr * Ff + c2) = pack_bf16(d[nb2][2]+bb0, d[nb2][3]+bb1);
        }
    }
}

// ========== bf16 edge kernel — 64-edge tile, 2 CTAs/SM, bf16 gathers, 5 syncs ======
#define STRA 144
#define STRB 272
#define OFF_WAT  0
#define OFF_WCT  18432
#define OFF_AN   79360
#define OFF_M    88576
#define OFF_WEXP 105984
#define OFF_SRC  108288
#define OFF_GE   108800
#define OFF_BE   109056
#define OFF_BD   109312
#define SMEDGE   109568

__global__ __launch_bounds__(512, 2) void k_edge(const float* __restrict__ ain,
                                                 const int* __restrict__ edges,
                                                 const float* __restrict__ w_a,
                                                 const float* __restrict__ w_vatt,
                                                 const float* __restrict__ w_edge,
                                                 const float* __restrict__ gain_e,
                                                 const float* __restrict__ bias_e,
                                                 const float* __restrict__ b_edge,
                                                 float* __restrict__ aout) {
    extern __shared__ __align__(16) char smem_raw[];
    const uint32_t smemU = (uint32_t)__cvta_generic_to_shared(smem_raw);
    const int tid = threadIdx.x;
    const int warp = tid >> 5, lane = tid & 31;
    const int g = lane >> 2, tg = lane & 3;
    const int wr = warp & 3;
    const int wq = warp >> 2;

    float* wexp_s = (float*)(smem_raw + OFF_WEXP);
    int*   src_s  = (int*)(smem_raw + OFF_SRC);
    float* ge_s   = (float*)(smem_raw + OFF_GE);
    float* be_s   = (float*)(smem_raw + OFF_BE);
    float* bd_s   = (float*)(smem_raw + OFF_BD);

    const uint32_t a4A = ((lane & 7) + ((lane >> 3) & 1) * 8) * STRA + ((lane >> 4) & 1) * 16;
    const uint32_t b4A = ((lane & 7) + ((lane >> 4) & 1) * 8) * STRA + ((lane >> 3) & 1) * 16;
    const uint32_t a4B = ((lane & 7) + ((lane >> 3) & 1) * 8) * STRB + ((lane >> 4) & 1) * 16;
    const uint32_t b4B = ((lane & 7) + ((lane >> 4) & 1) * 8) * STRB + ((lane >> 3) & 1) * 16;
    const uint32_t x2B = (lane & 7) * STRB + ((lane >> 3) & 1) * 16;

    for (int i = tid; i < 128 * 64; i += 512) {
        int n = i & 127, k = i >> 7;
        *(__nv_bfloat16*)(smem_raw + OFF_WAT + n * STRA + k * 2) =
            __float2bfloat16(w_a[k * Ff + n]);
    }
    for (int i = tid; i < 224 * 128; i += 512) {
        int n = i % 224, k = i / 224;
        float v = 0.f;
        if (n < 136)               v = w_vatt[k * 136 + n];
        else if (n < 200)          v = w_edge[k * EFe + (n - 136)];
        *(__nv_bfloat16*)(smem_raw + OFF_WCT + n * STRB + k * 2) = __float2bfloat16(v);
    }
    if (tid < EFe) { ge_s[tid] = gain_e[tid]; be_s[tid] = bias_e[tid]; bd_s[tid] = b_edge[tid]; }
    __syncthreads();

    for (int tile = blockIdx.x; tile < NTILES; tile += gridDim.x) {
        const int e0 = tile * ETILE;

        if (tid < ETILE) src_s[tid] = edges[e0 + tid];

        // ---- LN(a) -> an (bf16) ----
        #pragma unroll
        for (int q = 0; q < 4; q++) {
            int r = warp * 4 + q;
            float2 x = *(const float2*)(ain + (size_t)(e0 + r) * EFe + 2 * lane);
            float s = x.x + x.y;
            float ss = fmaf(x.x, x.x, x.y * x.y);
            #pragma unroll
            for (int o = 16; o > 0; o >>= 1) {
                s  += __shfl_xor_sync(0xffffffffu, s, o);
                ss += __shfl_xor_sync(0xffffffffu, ss, o);
            }
            float mu = s * (1.f / EFe);
            float rstd = rsqrtf(ss * (1.f / EFe) - mu * mu + 1e-5f);
            float v0 = (x.x - mu) * rstd * ge_s[2 * lane]     + be_s[2 * lane];
            float v1 = (x.y - mu) * rstd * ge_s[2 * lane + 1] + be_s[2 * lane + 1];
            *(uint32_t*)(smem_raw + OFF_AN + r * STRA + lane * 4) = pack_bf16(v0, v1);
        }

        // ---- hsum = hsrc[src] + hdst[dst] -> m_s (bf16 gathers) ----
        #pragma unroll
        for (int q = 0; q < 4; q++) {
            int r = warp * 4 + q;
            int sr = __ldg(edges + e0 + r);
            int dr = __ldg(edges + Ee + e0 + r);
            uint2 hs = *(const uint2*)(g_hsrcB + (size_t)sr * Ff + lane * 4);
            uint2 hd = *(const uint2*)(g_hdstB + (size_t)dr * Ff + lane * 4);
            float2 s0f = unpack_bf16(hs.x), s1f = unpack_bf16(hs.y);
            float2 d0f = unpack_bf16(hd.x), d1f = unpack_bf16(hd.y);
            uint2 p;
            p.x = pack_bf16(s0f.x + d0f.x, s0f.y + d0f.y);
            p.y = pack_bf16(s1f.x + d1f.x, s1f.y + d1f.y);
            *(uint2*)(smem_raw + OFF_M + r * STRB + lane * 8) = p;
        }
        __syncthreads();   // sync1

        const int row0 = wr * 16 + g, row1 = row0 + 8;
        const int s0 = src_s[row0], s1 = src_s[row1];

        // ---- GEMM1 ----
        float d1[4][4];
        #pragma unroll
        for (int i = 0; i < 4; i++) { d1[i][0]=0.f; d1[i][1]=0.f; d1[i][2]=0.f; d1[i][3]=0.f; }
        {
            const uint32_t aBase = smemU + OFF_AN + wr * 16 * STRA + a4A;
            #pragma unroll
            for (int ks = 0; ks < 4; ks++) {
                uint32_t a0, a1, a2, a3;
                ldsm_x4(a0, a1, a2, a3, aBase + ks * 32);
                #pragma unroll
                for (int np = 0; np < 2; np++) {
                    int n0 = wq * 32 + np * 16;
                    uint32_t b0, b1, b2, b3;
                    ldsm_x4(b0, b1, b2, b3, smemU + OFF_WAT + n0 * STRA + b4A + ks * 32);
                    mma_bf16(d1[2 * np],     a0, a1, a2, a3, b0, b1);
                    mma_bf16(d1[2 * np + 1], a0, a1, a2, a3, b2, b3);
                }
            }
        }

        // ---- epilogue 1: m = silu(D1 + hsum) in place ----
        #pragma unroll
        for (int nb = 0; nb < 4; nb++) {
            int col = wq * 32 + nb * 8 + 2 * tg;
            float2 h0 = unpack_bf16(*(const uint32_t*)(smem_raw + OFF_M + row0 * STRB + col * 2));
            float2 h1 = unpack_bf16(*(const uint32_t*)(smem_raw + OFF_M + row1 * STRB + col * 2));
            float m00 = siluf(d1[nb][0] + h0.x);
            float m01 = siluf(d1[nb][1] + h0.y);
            float m10 = siluf(d1[nb][2] + h1.x);
            float m11 = siluf(d1[nb][3] + h1.y);
            *(uint32_t*)(smem_raw + OFF_M + row0 * STRB + col * 2) = pack_bf16(m00, m01);
            *(uint32_t*)(smem_raw + OFF_M + row1 * STRB + col * 2) = pack_bf16(m10, m11);
        }
        __syncthreads();   // sync2: m ready

        // ---- GEMM2 ----
        float d2[7][4];
        #pragma unroll
        for (int i = 0; i < 7; i++) { d2[i][0]=0.f; d2[i][1]=0.f; d2[i][2]=0.f; d2[i][3]=0.f; }
        {
            const uint32_t aBase = smemU + OFF_M + wr * 16 * STRB + a4B;
            #pragma unroll
            for (int ks = 0; ks < 8; ks++) {
                uint32_t a0, a1, a2, a3;
                ldsm_x4(a0, a1, a2, a3, aBase + ks * 32);
                #pragma unroll
                for (int np = 0; np < 3; np++) {
                    int n0 = wq * 56 + np * 16;
                    uint32_t b0, b1, b2, b3;
                    ldsm_x4(b0, b1, b2, b3, smemU + OFF_WCT + n0 * STRB + b4B + ks * 32);
                    mma_bf16(d2[2 * np],     a0, a1, a2, a3, b0, b1);
                    mma_bf16(d2[2 * np + 1], a0, a1, a2, a3, b2, b3);
                }
                {
                    int n0 = wq * 56 + 48;
                    uint32_t b0, b1;
                    ldsm_x2(b0, b1, smemU + OFF_WCT + n0 * STRB + x2B + ks * 32);
                    mma_bf16(d2[6], a0, a1, a2, a3, b0, b1);
                }
            }
        }

        if (wq == 2) {
            int h = 2 * tg;
            float e00 = __expf(d2[2][0]);
            float e01 = __expf(d2[2][1]);
            float e10 = __expf(d2[2][2]);
            float e11 = __expf(d2[2][3]);
            wexp_s[row0 * 9 + h]     = e00;
            wexp_s[row0 * 9 + h + 1] = e01;
            wexp_s[row1 * 9 + h]     = e10;
            wexp_s[row1 * 9 + h + 1] = e11;
            float* p0 = g_wsum + (size_t)s0 * Hh + h;
            float* p1 = g_wsum + (size_t)s1 * Hh + h;
            asm volatile("red.global.add.f32 [%0], %1;" :: "l"(p0),     "f"(e00) : "memory");
            asm volatile("red.global.add.f32 [%0], %1;" :: "l"(p0 + 1), "f"(e01) : "memory");
            asm volatile("red.global.add.f32 [%0], %1;" :: "l"(p1),     "f"(e10) : "memory");
            asm volatile("red.global.add.f32 [%0], %1;" :: "l"(p1 + 1), "f"(e11) : "memory");
        }
        __syncthreads();   // sync3

        // ---- v-stage: wexp*v -> m_s; da -> an buffer ----
        #pragma unroll
        for (int nb = 0; nb < 7; nb++) {
            int col = wq * 56 + nb * 8 + 2 * tg;
            if (col < Ff) {
                int h = col >> 4;
                float w0 = wexp_s[row0 * 9 + h];
                float w1 = wexp_s[row1 * 9 + h];
                *(uint32_t*)(smem_raw + OFF_M + row0 * STRB + col * 2) =
                    pack_bf16(d2[nb][0] * w0, d2[nb][1] * w0);
                *(uint32_t*)(smem_raw + OFF_M + row1 * STRB + col * 2) =
                    pack_bf16(d2[nb][2] * w1, d2[nb][3] * w1);
            } else if (col >= 136 && col < 200) {
                int k2 = col - 136;
                *(uint32_t*)(smem_raw + OFF_AN + row0 * STRA + k2 * 2) =
                    pack_bf16(d2[nb][0], d2[nb][1]);
                *(uint32_t*)(smem_raw + OFF_AN + row1 * STRA + k2 * 2) =
                    pack_bf16(d2[nb][2], d2[nb][3]);
            }
        }
        __syncthreads();   // sync4

        // ---- cooperative coalesced epilogues ----
        #pragma unroll
        for (int q = 0; q < 4; q++) {
            int r = warp * 4 + q;
            int sr = src_s[r];
            uint2 p = *(const uint2*)(smem_raw + OFF_M + r * STRB + lane * 8);
            float2 v01 = unpack_bf16(p.x);
            float2 v23 = unpack_bf16(p.y);
            float* ob = g_o + (size_t)sr * Ff + lane * 4;
            asm volatile("red.global.add.v4.f32 [%0], {%1, %2, %3, %4};"
                         :: "l"(ob), "f"(v01.x), "f"(v01.y), "f"(v23.x), "f"(v23.y)
                         : "memory");
            float2 da = unpack_bf16(*(const uint32_t*)(smem_raw + OFF_AN + r * STRA + lane * 4));
            float2 av = *(const float2*)(ain + (size_t)(e0 + r) * EFe + 2 * lane);
            float2 ro;
            ro.x = av.x + da.x + bd_s[2 * lane];
            ro.y = av.y + da.y + bd_s[2 * lane + 1];
            *(float2*)(aout + (size_t)(e0 + r) * EFe + 2 * lane) = ro;
        }
        __syncthreads();   // sync5
    }
}

// ============== fused node kernel 2 + MLP (double-buffered cp.async weights) =======
#define N2STR 272
#define OFF2_W  0
#define OFF2_W2 34816
#define OFF2_XN 69632
#define OFF2_T  104448
#define OFF2_HM 139264
#define SM_N2M  208896

__global__ __launch_bounds__(512) void k_node2mlp(const float* __restrict__ input,
                                                  const int* __restrict__ batch,
                                                  const float* __restrict__ b_out,
                                                  const float* __restrict__ b1,
                                                  const float* __restrict__ b2,
                                                  float* __restrict__ hout) {
    extern __shared__ __align__(16) char smem_raw[];
    const uint32_t smemU = (uint32_t)__cvta_generic_to_shared(smem_raw);
    const int tid = threadIdx.x;
    const int warp = tid >> 5, lane = tid & 31;
    const int g = lane >> 2, tg = lane & 3;
    const int wr = warp & 7, wq = warp >> 3;
    const int nb = blockIdx.x * NTILE;
    char* xnb  = smem_raw + OFF2_XN;
    char* tb   = smem_raw + OFF2_T;
    float* hm_s = (float*)(smem_raw + OFF2_HM);

    const uint32_t a4 = ((lane & 7) + ((lane >> 3) & 1) * 8) * N2STR + ((lane >> 4) & 1) * 16;
    const uint32_t b4 = ((lane & 7) + ((lane >> 4) & 1) * 8) * N2STR + ((lane >> 3) & 1) * 16;
    const uint32_t aRow = wr * 16 * N2STR + a4;

    for (int i = tid; i < 2048; i += 512) {
        int n = i >> 4, k16 = i & 15;
        cp16(smemU + OFF2_W + n * N2STR + k16 * 16, pbO + n * 128 + k16 * 8);
    }
    CP_COMMIT();
    for (int i = tid; i < 2048; i += 512) {
        int n = i >> 4, k16 = i & 15;
        cp16(smemU + OFF2_W2 + n * N2STR + k16 * 16, pb1 + n * 128 + k16 * 8);
    }
    CP_COMMIT();

    for (int i = tid; i < NTILE * 32; i += 512) {
        int r = i >> 5, c4 = i & 31;
        int n = nb + r;
        int nc = n < Nn ? n : Nn - 1;
        float4 o4 = ((const float4*)(g_o + (size_t)nc * Ff))[c4];
        int h = c4 >> 2;
        float inv = 1.f / (g_wsum[nc * Hh + h] + 1e-16f);
        *(uint32_t*)(tb + r * N2STR + c4 * 8)     = pack_bf16(o4.x * inv, o4.y * inv);
        *(uint32_t*)(tb + r * N2STR + c4 * 8 + 4) = pack_bf16(o4.z * inv, o4.w * inv);
    }
    CP_WAIT(1);
    __syncthreads();

    const int row0 = wr * 16 + g, row1 = row0 + 8;
    const int na = nb + row0, nb1 = nb + row1;
    const int nca = na < Nn ? na : Nn - 1;
    const int ncb = nb1 < Nn ? nb1 : Nn - 1;

    {
        float d[8][4];
        #pragma unroll
        for (int i = 0; i < 8; i++) { d[i][0]=0.f; d[i][1]=0.f; d[i][2]=0.f; d[i][3]=0.f; }
        #pragma unroll
        for (int ks = 0; ks < 8; ks++) {
            uint32_t a0, a1, a2, a3;
            ldsm_x4(a0, a1, a2, a3, smemU + OFF2_T + aRow + ks * 32);
            #pragma unroll
            for (int np = 0; np < 4; np++) {
                int n0 = wq * 64 + np * 16;
                uint32_t b0, b1, b2, b3;
                ldsm_x4(b0, b1, b2, b3, smemU + OFF2_W + n0 * N2STR + b4 + ks * 32);
                mma_bf16(d[2 * np],     a0, a1, a2, a3, b0, b1);
                mma_bf16(d[2 * np + 1], a0, a1, a2, a3, b2, b3);
            }
        }
        #pragma unroll
        for (int nb2 = 0; nb2 < 8; nb2++) {
            int c = wq * 64 + nb2 * 8 + 2 * tg;
            float2 ia = *(const float2*)(input + (size_t)nca * Ff + c);
            float2 ib = *(const float2*)(input + (size_t)ncb * Ff + c);
            float bb0 = __ldg(b_out + c), bb1 = __ldg(b_out + c + 1);
            hm_s[row0 * 136 + c]     = d[nb2][0] + ia.x + bb0;
            hm_s[row0 * 136 + c + 1] = d[nb2][1] + ia.y + bb1;
            hm_s[row1 * 136 + c]     = d[nb2][2] + ib.x + bb0;
            hm_s[row1 * 136 + c + 1] = d[nb2][3] + ib.y + bb1;
        }
    }
    __syncthreads();

    #pragma unroll
    for (int q = 0; q < 8; q++) {
        int r = warp * 8 + q;
        int n = nb + r;
        int nc = n < Nn ? n : Nn - 1;
        float4 x = ((const float4*)(hm_s + r * 136))[lane];
        float s  = x.x + x.y + x.z + x.w;
        float ss = fmaf(x.x, x.x, fmaf(x.y, x.y, fmaf(x.z, x.z, x.w * x.w)));
        #pragma unroll
        for (int o = 16; o > 0; o >>= 1) {
            s  += __shfl_xor_sync(0xffffffffu, s, o);
            ss += __shfl_xor_sync(0xffffffffu, ss, o);
        }
        float mu = s * (1.f / Ff);
        float rstd = rsqrtf(ss * (1.f / Ff) - mu * mu + 1e-5f);
        int bix = batch[nc];
        const float* sb = g_sb_mlp + bix * F2;
        float4 sc = *((const float4*)(sb + lane * 4));
        float4 sh = *((const float4*)(sb + Ff + lane * 4));
        float o0 = (x.x - mu) * rstd * (1.f + sc.x) + sh.x;
        float o1 = (x.y - mu) * rstd * (1.f + sc.y) + sh.y;
        float o2 = (x.z - mu) * rstd * (1.f + sc.z) + sh.z;
        float o3 = (x.w - mu) * rstd * (1.f + sc.w) + sh.w;
        *(uint32_t*)(xnb + r * N2STR + lane * 8)     = pack_bf16(o0, o1);
        *(uint32_t*)(xnb + r * N2STR + lane * 8 + 4) = pack_bf16(o2, o3);
    }

    float oacc[8][4];
    #pragma unroll
    for (int i = 0; i < 8; i++) { oacc[i][0]=0.f; oacc[i][1]=0.f; oacc[i][2]=0.f; oacc[i][3]=0.f; }

    for (int ch = 0; ch < 4; ch++) {
        __syncthreads();
        for (int i = tid; i < 2048; i += 512) {
            int n = i >> 4, k16 = i & 15;
            cp16(smemU + OFF2_W + n * N2STR + k16 * 16, pb2 + n * 512 + ch * 128 + k16 * 8);
        }
        CP_COMMIT();
        CP_WAIT(1);
        __syncthreads();

        float dt[8][4];
        #pragma unroll
        for (int i = 0; i < 8; i++) { dt[i][0]=0.f; dt[i][1]=0.f; dt[i][2]=0.f; dt[i][3]=0.f; }
        #pragma unroll
        for (int ks = 0; ks < 8; ks++) {
            uint32_t a0, a1, a2, a3;
            ldsm_x4(a0, a1, a2, a3, smemU + OFF2_XN + aRow + ks * 32);
            #pragma unroll
            for (int np = 0; np < 4; np++) {
                int n0 = wq * 64 + np * 16;
                uint32_t b0, b1, b2, b3;
                ldsm_x4(b0, b1, b2, b3, smemU + OFF2_W2 + n0 * N2STR + b4 + ks * 32);
                mma_bf16(dt[2 * np],     a0, a1, a2, a3, b0, b1);
                mma_bf16(dt[2 * np + 1], a0, a1, a2, a3, b2, b3);
            }
        }
        #pragma unroll
        for (int nb2 = 0; nb2 < 8; nb2++) {
            int c = wq * 64 + nb2 * 8 + 2 * tg;
            float b10 = __ldg(b1 + ch * 128 + c), b11 = __ldg(b1 + ch * 128 + c + 1);
            *(uint32_t*)(tb + row0 * N2STR + c * 2) =
                pack_bf16(siluf(dt[nb2][0] + b10), siluf(dt[nb2][1] + b11));
            *(uint32_t*)(tb + row1 * N2STR + c * 2) =
                pack_bf16(siluf(dt[nb2][2] + b10), siluf(dt[nb2][3] + b11));
        }
        __syncthreads();
        if (ch < 3) {
            for (int i = tid; i < 2048; i += 512) {
                int n = i >> 4, k16 = i & 15;
                cp16(smemU + OFF2_W2 + n * N2STR + k16 * 16,
                     pb1 + (size_t)(ch + 1) * 128 * 128 + n * 128 + k16 * 8);
            }
            CP_COMMIT();
            CP_WAIT(1);
        } else {
            CP_WAIT(0);
        }
        __syncthreads();

        #pragma unroll
        for (int ks = 0; ks < 8; ks++) {
            uint32_t a0, a1, a2, a3;
            ldsm_x4(a0, a1, a2, a3, smemU + OFF2_T + aRow + ks * 32);
            #pragma unroll
            for (int np = 0; np < 4; np++) {
                int n0 = wq * 64 + np * 16;
                uint32_t b0, b1, b2, b3;
                ldsm_x4(b0, b1, b2, b3, smemU + OFF2_W + n0 * N2STR + b4 + ks * 32);
                mma_bf16(oacc[2 * np],     a0, a1, a2, a3, b0, b1);
                mma_bf16(oacc[2 * np + 1], a0, a1, a2, a3, b2, b3);
            }
        }
    }

    #pragma unroll
    for (int nb2 = 0; nb2 < 8; nb2++) {
        int c = wq * 64 + nb2 * 8 + 2 * tg;
        float b20 = __ldg(b2 + c), b21 = __ldg(b2 + c + 1);
        if (na < Nn) {
            float2 v = {oacc[nb2][0] + hm_s[row0 * 136 + c]     + b20,
                        oacc[nb2][1] + hm_s[row0 * 136 + c + 1] + b21};
            *(float2*)(hout + (size_t)na * Ff + c) = v;
        }
        if (nb1 < Nn) {
            float2 v = {oacc[nb2][2] + hm_s[row1 * 136 + c]     + b20,
                        oacc[nb2][3] + hm_s[row1 * 136 + c + 1] + b21};
            *(float2*)(hout + (size_t)nb1 * Ff + c) = v;
        }
    }
}

// ---------------- launcher ---------------------------------------------------------
extern "C" void kernel_launch(void* const* d_in, const int* in_sizes, int n_in,
                              void* d_out, int out_size) {
    const float* input     = (const float*)d_in[0];
    const float* cond      = (const float*)d_in[1];
    const float* a         = (const float*)d_in[2];
    const int*   batch     = (const int*)d_in[3];
    const int*   edges     = (const int*)d_in[4];
    const float* w_ada_mix = (const float*)d_in[5];
    const float* b_ada_mix = (const float*)d_in[6];
    const float* w_h       = (const float*)d_in[7];
    const float* b_h       = (const float*)d_in[8];
    const float* w_a       = (const float*)d_in[9];
    const float* w_vatt    = (const float*)d_in[10];
    const float* w_out     = (const float*)d_in[11];
    const float* b_out     = (const float*)d_in[12];
    const float* g_edge_p  = (const float*)d_in[13];
    const float* be_edge_p = (const float*)d_in[14];
    const float* w_edge    = (const float*)d_in[15];
    const float* b_edge    = (const float*)d_in[16];
    const float* w_ada_mlp = (const float*)d_in[17];
    const float* b_ada_mlp = (const float*)d_in[18];
    const float* w1        = (const float*)d_in[19];
    const float* b1        = (const float*)d_in[20];
    const float* w2        = (const float*)d_in[21];
    const float* b2        = (const float*)d_in[22];

    float* hout = (float*)d_out;                       // h: [N, F]
    float* aout = (float*)d_out + (size_t)Nn * Ff;     // a_out: [E, EF]

    cudaFuncSetAttribute(k_node1,    cudaFuncAttributeMaxDynamicSharedMemorySize, SM_NODE1);
    cudaFuncSetAttribute(k_edge,     cudaFuncAttributeMaxDynamicSharedMemorySize, SMEDGE);
    cudaFuncSetAttribute(k_node2mlp, cudaFuncAttributeMaxDynamicSharedMemorySize, SM_N2M);

    const int NT = (Nn + NTILE - 1) / NTILE;  // 157

    k_init<<<(Nn * Ff + 255) / 256, 256>>>();
    k_prep<<<176, 256>>>(w_h, w_out, w1, w2);
    k_cond<<<dim3(Gg, 2), 256>>>(cond, w_ada_mix, b_ada_mix, w_ada_mlp, b_ada_mlp);
    k_node1<<<NT, 512, SM_NODE1>>>(input, batch, b_h);
    k_edge<<<296, 512, SMEDGE>>>(a, edges, w_a, w_vatt, w_edge,
                                 g_edge_p, be_edge_p, b_edge, aout);
    k_node2mlp<<<NT, 512, SM_N2M>>>(input, batch, b_out, b1, b2, hout);
}

// round 17
// speedup vs baseline: 1.1577x; 1.1015x over previous
#include <cuda_runtime.h>
#include <cuda_bf16.h>
#include <cstdint>
#include <cstddef>

#define Nn 20000
#define Ee 320000
#define Ff 128
#define Hh 8
#define EFe 64
#define Aa 128
#define Gg 32
#define F2 256
#define NTILE 128
#define N2TILE 64
#define ETILE 64
#define NTILES (Ee / ETILE)

// ---------------- scratch (device globals; no allocations allowed) ----------------
__device__ float g_sb_mix[Gg * F2];
__device__ float g_sb_mlp[Gg * F2];
__device__ __nv_bfloat16 g_hsrcB[(size_t)Nn * Ff];
__device__ __nv_bfloat16 g_hdstB[(size_t)Nn * Ff];
__device__ float g_wsum[Nn * Hh];
__device__ float g_o[(size_t)Nn * Ff];
// prepacked bf16 transposed weights
__device__ __nv_bfloat16 pbH[256 * 128];
__device__ __nv_bfloat16 pbO[128 * 128];
__device__ __nv_bfloat16 pb1[512 * 128];
__device__ __nv_bfloat16 pb2[128 * 512];

__device__ __forceinline__ float siluf(float x) { return x / (1.f + __expf(-x)); }

__device__ __forceinline__ void mma_bf16(float* d, uint32_t a0, uint32_t a1,
                                         uint32_t a2, uint32_t a3,
                                         uint32_t b0, uint32_t b1) {
    asm volatile(
        "mma.sync.aligned.m16n8k16.row.col.f32.bf16.bf16.f32 "
        "{%0,%1,%2,%3}, {%4,%5,%6,%7}, {%8,%9}, {%0,%1,%2,%3};"
        : "+f"(d[0]), "+f"(d[1]), "+f"(d[2]), "+f"(d[3])
        : "r"(a0), "r"(a1), "r"(a2), "r"(a3), "r"(b0), "r"(b1));
}

__device__ __forceinline__ void ldsm_x4(uint32_t& r0, uint32_t& r1,
                                        uint32_t& r2, uint32_t& r3, uint32_t addr) {
    asm volatile("ldmatrix.sync.aligned.m8n8.x4.shared.b16 {%0,%1,%2,%3}, [%4];"
                 : "=r"(r0), "=r"(r1), "=r"(r2), "=r"(r3) : "r"(addr));
}
__device__ __forceinline__ void ldsm_x2(uint32_t& r0, uint32_t& r1, uint32_t addr) {
    asm volatile("ldmatrix.sync.aligned.m8n8.x2.shared.b16 {%0,%1}, [%2];"
                 : "=r"(r0), "=r"(r1) : "r"(addr));
}

__device__ __forceinline__ void cp16(uint32_t dst, const void* src) {
    asm volatile("cp.async.cg.shared.global [%0], [%1], 16;" :: "r"(dst), "l"(src));
}
#define CP_COMMIT() asm volatile("cp.async.commit_group;" ::: "memory")
#define CP_WAIT(N)  asm volatile("cp.async.wait_group %0;" :: "n"(N) : "memory")

__device__ __forceinline__ uint32_t pack_bf16(float a, float b) {
    __nv_bfloat162 p = __floats2bfloat162_rn(a, b);
    return *(uint32_t*)&p;
}
__device__ __forceinline__ float2 unpack_bf16(uint32_t u) {
    __nv_bfloat162 p = *(__nv_bfloat162*)&u;
    return make_float2(__bfloat162float(p.x), __bfloat162float(p.y));
}

// ---- merged setup kernel: init (blocks 0..9999) | prep (10000..10175) | cond ------
__global__ __launch_bounds__(256) void k_setup(const float* __restrict__ w_h,
                                               const float* __restrict__ w_out,
                                               const float* __restrict__ w1,
                                               const float* __restrict__ w2,
                                               const float* __restrict__ cond,
                                               const float* __restrict__ w_mix,
                                               const float* __restrict__ b_mix,
                                               const float* __restrict__ w_mlp,
                                               const float* __restrict__ b_mlp) {
    __shared__ float sh[32 * 33];
    int b = blockIdx.x;
    int t = threadIdx.x;
    if (b < 10000) {
        int i = b * 256 + t;
        if (i < Nn * Ff) g_o[i] = 0.f;
        if (i < Nn * Hh) g_wsum[i] = 0.f;
        return;
    }
    if (b < 10176) {
        b -= 10000;
        const float* src; __nv_bfloat16* dst; int K, N, tk, tn;
        if (b < 32)       { src = w_h;   dst = pbH; K = 128; N = 256; tk = b & 3;  tn = b >> 2; }
        else if (b < 48)  { b -= 32;  src = w_out; dst = pbO; K = 128; N = 128; tk = b & 3;  tn = b >> 2; }
        else if (b < 112) { b -= 48;  src = w1;    dst = pb1; K = 128; N = 512; tk = b & 3;  tn = b >> 2; }
        else              { b -= 112; src = w2;    dst = pb2; K = 512; N = 128; tk = b & 15; tn = b >> 4; }
        int k0 = tk * 32, n0 = tn * 32;
        int lx = t & 31, ly = t >> 5;
        #pragma unroll
        for (int j = 0; j < 32; j += 8)
            sh[(ly + j) * 33 + lx] = src[(size_t)(k0 + ly + j) * N + n0 + lx];
        __syncthreads();
        #pragma unroll
        for (int j = 0; j < 32; j += 8)
            dst[(size_t)(n0 + ly + j) * K + k0 + lx] = __float2bfloat16(sh[lx * 33 + ly + j]);
        return;
    }
    {
        int idx = b - 10176;
        int g = idx & 31, which = idx >> 5;
        const float* w = which ? w_mlp : w_mix;
        const float* bb = which ? b_mlp : b_mix;
        float* outp = which ? g_sb_mlp : g_sb_mix;
        if (t < Aa) sh[t] = cond[g * Aa + t];
        __syncthreads();
        float acc = bb[t];
        #pragma unroll 8
        for (int k = 0; k < Aa; k++) acc = fmaf(sh[k], w[k * F2 + t], acc);
        outp[g * F2 + t] = acc;
    }
}

// ============== node kernel 1 (HMMA, 128-row tile, 2 CTA/SM, cp.async W) ===========
#define N1STR 272
#define N1_OFF_XM 0
#define N1_OFF_W  34816
#define SM_NODE1  104448

__global__ __launch_bounds__(512, 2) void k_node1(const float* __restrict__ input,
                                                  const int* __restrict__ batch,
                                                  const float* __restrict__ b_h) {
    extern __shared__ __align__(16) char smem_raw[];
    const uint32_t smemU = (uint32_t)__cvta_generic_to_shared(smem_raw);
    const int tid = threadIdx.x;
    const int warp = tid >> 5, lane = tid & 31;
    const int nb = blockIdx.x * NTILE;
    char* xm = smem_raw + N1_OFF_XM;

    const uint32_t a4 = ((lane & 7) + ((lane >> 3) & 1) * 8) * N1STR + ((lane >> 4) & 1) * 16;
    const uint32_t b4 = ((lane & 7) + ((lane >> 4) & 1) * 8) * N1STR + ((lane >> 3) & 1) * 16;

    for (int i = tid; i < 256 * 16; i += 512) {
        int n = i >> 4, k16 = i & 15;
        cp16(smemU + N1_OFF_W + n * N1STR + k16 * 16, pbH + n * 128 + k16 * 8);
    }
    CP_COMMIT();

    #pragma unroll
    for (int q = 0; q < 8; q++) {
        int r = warp * 8 + q;
        int n = nb + r;
        int nc = n < Nn ? n : Nn - 1;
        float4 x = ((const float4*)(input + (size_t)nc * Ff))[lane];
        float s  = x.x + x.y + x.z + x.w;
        float ss = fmaf(x.x, x.x, fmaf(x.y, x.y, fmaf(x.z, x.z, x.w * x.w)));
        #pragma unroll
        for (int o = 16; o > 0; o >>= 1) {
            s  += __shfl_xor_sync(0xffffffffu, s, o);
            ss += __shfl_xor_sync(0xffffffffu, ss, o);
        }
        float mu = s * (1.f / Ff);
        float rstd = rsqrtf(ss * (1.f / Ff) - mu * mu + 1e-5f);
        int bix = batch[nc];
        const float* sb = g_sb_mix + bix * F2;
        float4 sc = *((const float4*)(sb + lane * 4));
        float4 sh = *((const float4*)(sb + Ff + lane * 4));
        float o0 = (x.x - mu) * rstd * (1.f + sc.x) + sh.x;
        float o1 = (x.y - mu) * rstd * (1.f + sc.y) + sh.y;
        float o2 = (x.z - mu) * rstd * (1.f + sc.z) + sh.z;
        float o3 = (x.w - mu) * rstd * (1.f + sc.w) + sh.w;
        *(uint32_t*)(xm + r * N1STR + lane * 8)     = pack_bf16(o0, o1);
        *(uint32_t*)(xm + r * N1STR + lane * 8 + 4) = pack_bf16(o2, o3);
    }
    CP_WAIT(0);
    __syncthreads();

    const int wr = warp & 7, wq = warp >> 3;
    const int row0 = wr * 16 + (lane >> 2);
    const int na = nb + row0, nbr = na + 8;
    const uint32_t aBase = smemU + N1_OFF_XM + wr * 16 * N1STR + a4;
    const int tg = lane & 3;

    #pragma unroll
    for (int npass = 0; npass < 2; npass++) {
        float d[8][4];
        #pragma unroll
        for (int i = 0; i < 8; i++) { d[i][0]=0.f; d[i][1]=0.f; d[i][2]=0.f; d[i][3]=0.f; }
        #pragma unroll
        for (int ks = 0; ks < 8; ks++) {
            uint32_t a0, a1, a2, a3;
            ldsm_x4(a0, a1, a2, a3, aBase + ks * 32);
            #pragma unroll
            for (int np = 0; np < 4; np++) {
                int n0 = npass * 128 + wq * 64 + np * 16;
                uint32_t b0, b1, b2, b3;
                ldsm_x4(b0, b1, b2, b3, smemU + N1_OFF_W + n0 * N1STR + b4 + ks * 32);
                mma_bf16(d[2 * np],     a0, a1, a2, a3, b0, b1);
                mma_bf16(d[2 * np + 1], a0, a1, a2, a3, b2, b3);
            }
        }
        __nv_bfloat16* gout = (npass == 0) ? g_hsrcB : g_hdstB;
        #pragma unroll
        for (int nb2 = 0; nb2 < 8; nb2++) {
            int c = npass * 128 + wq * 64 + nb2 * 8 + 2 * tg;
            float bb0 = __ldg(b_h + c), bb1 = __ldg(b_h + c + 1);
            int c2 = c - npass * 128;
            if (na < Nn)
                *(uint32_t*)(gout + (size_t)na * Ff + c2) = pack_bf16(d[nb2][0]+bb0, d[nb2][1]+bb1);
            if (nbr < Nn)
                *(uint32_t*)(gout + (size_t)nbr * Ff + c2) = pack_bf16(d[nb2][2]+bb0, d[nb2][3]+bb1);
        }
    }
}

// ========== bf16 edge kernel — 64-edge tile, 2 CTAs/SM, bf16 gathers (unchanged) ===
#define STRA 144
#define STRB 272
#define OFF_WAT  0
#define OFF_WCT  18432
#define OFF_AN   79360
#define OFF_M    88576
#define OFF_WEXP 105984
#define OFF_SRC  108288
#define OFF_GE   108800
#define OFF_BE   109056
#define OFF_BD   109312
#define SMEDGE   109568

__global__ __launch_bounds__(512, 2) void k_edge(const float* __restrict__ ain,
                                                 const int* __restrict__ edges,
                                                 const float* __restrict__ w_a,
                                                 const float* __restrict__ w_vatt,
                                                 const float* __restrict__ w_edge,
                                                 const float* __restrict__ gain_e,
                                                 const float* __restrict__ bias_e,
                                                 const float* __restrict__ b_edge,
                                                 float* __restrict__ aout) {
    extern __shared__ __align__(16) char smem_raw[];
    const uint32_t smemU = (uint32_t)__cvta_generic_to_shared(smem_raw);
    const int tid = threadIdx.x;
    const int warp = tid >> 5, lane = tid & 31;
    const int g = lane >> 2, tg = lane & 3;
    const int wr = warp & 3;
    const int wq = warp >> 2;

    float* wexp_s = (float*)(smem_raw + OFF_WEXP);
    int*   src_s  = (int*)(smem_raw + OFF_SRC);
    float* ge_s   = (float*)(smem_raw + OFF_GE);
    float* be_s   = (float*)(smem_raw + OFF_BE);
    float* bd_s   = (float*)(smem_raw + OFF_BD);

    const uint32_t a4A = ((lane & 7) + ((lane >> 3) & 1) * 8) * STRA + ((lane >> 4) & 1) * 16;
    const uint32_t b4A = ((lane & 7) + ((lane >> 4) & 1) * 8) * STRA + ((lane >> 3) & 1) * 16;
    const uint32_t a4B = ((lane & 7) + ((lane >> 3) & 1) * 8) * STRB + ((lane >> 4) & 1) * 16;
    const uint32_t b4B = ((lane & 7) + ((lane >> 4) & 1) * 8) * STRB + ((lane >> 3) & 1) * 16;
    const uint32_t x2B = (lane & 7) * STRB + ((lane >> 3) & 1) * 16;

    for (int i = tid; i < 128 * 64; i += 512) {
        int n = i & 127, k = i >> 7;
        *(__nv_bfloat16*)(smem_raw + OFF_WAT + n * STRA + k * 2) =
            __float2bfloat16(w_a[k * Ff + n]);
    }
    for (int i = tid; i < 224 * 128; i += 512) {
        int n = i % 224, k = i / 224;
        float v = 0.f;
        if (n < 136)               v = w_vatt[k * 136 + n];
        else if (n < 200)          v = w_edge[k * EFe + (n - 136)];
        *(__nv_bfloat16*)(smem_raw + OFF_WCT + n * STRB + k * 2) = __float2bfloat16(v);
    }
    if (tid < EFe) { ge_s[tid] = gain_e[tid]; be_s[tid] = bias_e[tid]; bd_s[tid] = b_edge[tid]; }
    __syncthreads();

    for (int tile = blockIdx.x; tile < NTILES; tile += gridDim.x) {
        const int e0 = tile * ETILE;

        if (tid < ETILE) src_s[tid] = edges[e0 + tid];

        #pragma unroll
        for (int q = 0; q < 4; q++) {
            int r = warp * 4 + q;
            float2 x = *(const float2*)(ain + (size_t)(e0 + r) * EFe + 2 * lane);
            float s = x.x + x.y;
            float ss = fmaf(x.x, x.x, x.y * x.y);
            #pragma unroll
            for (int o = 16; o > 0; o >>= 1) {
                s  += __shfl_xor_sync(0xffffffffu, s, o);
                ss += __shfl_xor_sync(0xffffffffu, ss, o);
            }
            float mu = s * (1.f / EFe);
            float rstd = rsqrtf(ss * (1.f / EFe) - mu * mu + 1e-5f);
            float v0 = (x.x - mu) * rstd * ge_s[2 * lane]     + be_s[2 * lane];
            float v1 = (x.y - mu) * rstd * ge_s[2 * lane + 1] + be_s[2 * lane + 1];
            *(uint32_t*)(smem_raw + OFF_AN + r * STRA + lane * 4) = pack_bf16(v0, v1);
        }

        #pragma unroll
        for (int q = 0; q < 4; q++) {
            int r = warp * 4 + q;
            int sr = __ldg(edges + e0 + r);
            int dr = __ldg(edges + Ee + e0 + r);
            uint2 hs = *(const uint2*)(g_hsrcB + (size_t)sr * Ff + lane * 4);
            uint2 hd = *(const uint2*)(g_hdstB + (size_t)dr * Ff + lane * 4);
            float2 s0f = unpack_bf16(hs.x), s1f = unpack_bf16(hs.y);
            float2 d0f = unpack_bf16(hd.x), d1f = unpack_bf16(hd.y);
            uint2 p;
            p.x = pack_bf16(s0f.x + d0f.x, s0f.y + d0f.y);
            p.y = pack_bf16(s1f.x + d1f.x, s1f.y + d1f.y);
            *(uint2*)(smem_raw + OFF_M + r * STRB + lane * 8) = p;
        }
        __syncthreads();   // sync1

        const int row0 = wr * 16 + g, row1 = row0 + 8;
        const int s0 = src_s[row0], s1 = src_s[row1];

        float d1[4][4];
        #pragma unroll
        for (int i = 0; i < 4; i++) { d1[i][0]=0.f; d1[i][1]=0.f; d1[i][2]=0.f; d1[i][3]=0.f; }
        {
            const uint32_t aBase = smemU + OFF_AN + wr * 16 * STRA + a4A;
            #pragma unroll
            for (int ks = 0; ks < 4; ks++) {
                uint32_t a0, a1, a2, a3;
                ldsm_x4(a0, a1, a2, a3, aBase + ks * 32);
                #pragma unroll
                for (int np = 0; np < 2; np++) {
                    int n0 = wq * 32 + np * 16;
                    uint32_t b0, b1, b2, b3;
                    ldsm_x4(b0, b1, b2, b3, smemU + OFF_WAT + n0 * STRA + b4A + ks * 32);
                    mma_bf16(d1[2 * np],     a0, a1, a2, a3, b0, b1);
                    mma_bf16(d1[2 * np + 1], a0, a1, a2, a3, b2, b3);
                }
            }
        }

        #pragma unroll
        for (int nb = 0; nb < 4; nb++) {
            int col = wq * 32 + nb * 8 + 2 * tg;
            float2 h0 = unpack_bf16(*(const uint32_t*)(smem_raw + OFF_M + row0 * STRB + col * 2));
            float2 h1 = unpack_bf16(*(const uint32_t*)(smem_raw + OFF_M + row1 * STRB + col * 2));
            float m00 = siluf(d1[nb][0] + h0.x);
            float m01 = siluf(d1[nb][1] + h0.y);
            float m10 = siluf(d1[nb][2] + h1.x);
            float m11 = siluf(d1[nb][3] + h1.y);
            *(uint32_t*)(smem_raw + OFF_M + row0 * STRB + col * 2) = pack_bf16(m00, m01);
            *(uint32_t*)(smem_raw + OFF_M + row1 * STRB + col * 2) = pack_bf16(m10, m11);
        }
        __syncthreads();   // sync2

        float d2[7][4];
        #pragma unroll
        for (int i = 0; i < 7; i++) { d2[i][0]=0.f; d2[i][1]=0.f; d2[i][2]=0.f; d2[i][3]=0.f; }
        {
            const uint32_t aBase = smemU + OFF_M + wr * 16 * STRB + a4B;
            #pragma unroll
            for (int ks = 0; ks < 8; ks++) {
                uint32_t a0, a1, a2, a3;
                ldsm_x4(a0, a1, a2, a3, aBase + ks * 32);
                #pragma unroll
                for (int np = 0; np < 3; np++) {
                    int n0 = wq * 56 + np * 16;
                    uint32_t b0, b1, b2, b3;
                    ldsm_x4(b0, b1, b2, b3, smemU + OFF_WCT + n0 * STRB + b4B + ks * 32);
                    mma_bf16(d2[2 * np],     a0, a1, a2, a3, b0, b1);
                    mma_bf16(d2[2 * np + 1], a0, a1, a2, a3, b2, b3);
                }
                {
                    int n0 = wq * 56 + 48;
                    uint32_t b0, b1;
                    ldsm_x2(b0, b1, smemU + OFF_WCT + n0 * STRB + x2B + ks * 32);
                    mma_bf16(d2[6], a0, a1, a2, a3, b0, b1);
                }
            }
        }

        if (wq == 2) {
            int h = 2 * tg;
            float e00 = __expf(d2[2][0]);
            float e01 = __expf(d2[2][1]);
            float e10 = __expf(d2[2][2]);
            float e11 = __expf(d2[2][3]);
            wexp_s[row0 * 9 + h]     = e00;
            wexp_s[row0 * 9 + h + 1] = e01;
            wexp_s[row1 * 9 + h]     = e10;
            wexp_s[row1 * 9 + h + 1] = e11;
            float* p0 = g_wsum + (size_t)s0 * Hh + h;
            float* p1 = g_wsum + (size_t)s1 * Hh + h;
            asm volatile("red.global.add.f32 [%0], %1;" :: "l"(p0),     "f"(e00) : "memory");
            asm volatile("red.global.add.f32 [%0], %1;" :: "l"(p0 + 1), "f"(e01) : "memory");
            asm volatile("red.global.add.f32 [%0], %1;" :: "l"(p1),     "f"(e10) : "memory");
            asm volatile("red.global.add.f32 [%0], %1;" :: "l"(p1 + 1), "f"(e11) : "memory");
        }
        __syncthreads();   // sync3

        #pragma unroll
        for (int nb = 0; nb < 7; nb++) {
            int col = wq * 56 + nb * 8 + 2 * tg;
            if (col < Ff) {
                int h = col >> 4;
                float w0 = wexp_s[row0 * 9 + h];
                float w1 = wexp_s[row1 * 9 + h];
                *(uint32_t*)(smem_raw + OFF_M + row0 * STRB + col * 2) =
                    pack_bf16(d2[nb][0] * w0, d2[nb][1] * w0);
                *(uint32_t*)(smem_raw + OFF_M + row1 * STRB + col * 2) =
                    pack_bf16(d2[nb][2] * w1, d2[nb][3] * w1);
            } else if (col >= 136 && col < 200) {
                int k2 = col - 136;
                *(uint32_t*)(smem_raw + OFF_AN + row0 * STRA + k2 * 2) =
                    pack_bf16(d2[nb][0], d2[nb][1]);
                *(uint32_t*)(smem_raw + OFF_AN + row1 * STRA + k2 * 2) =
                    pack_bf16(d2[nb][2], d2[nb][3]);
            }
        }
        __syncthreads();   // sync4

        #pragma unroll
        for (int q = 0; q < 4; q++) {
            int r = warp * 4 + q;
            int sr = src_s[r];
            uint2 p = *(const uint2*)(smem_raw + OFF_M + r * STRB + lane * 8);
            float2 v01 = unpack_bf16(p.x);
            float2 v23 = unpack_bf16(p.y);
            float* ob = g_o + (size_t)sr * Ff + lane * 4;
            asm volatile("red.global.add.v4.f32 [%0], {%1, %2, %3, %4};"
                         :: "l"(ob), "f"(v01.x), "f"(v01.y), "f"(v23.x), "f"(v23.y)
                         : "memory");
            float2 da = unpack_bf16(*(const uint32_t*)(smem_raw + OFF_AN + r * STRA + lane * 4));
            float2 av = *(const float2*)(ain + (size_t)(e0 + r) * EFe + 2 * lane);
            float2 ro;
            ro.x = av.x + da.x + bd_s[2 * lane];
            ro.y = av.y + da.y + bd_s[2 * lane + 1];
            *(float2*)(aout + (size_t)(e0 + r) * EFe + 2 * lane) = ro;
        }
        __syncthreads();   // sync5
    }
}

// ====== fused node kernel 2 + MLP — 64-row tile, 2 CTA/SM, single W buffer =========
#define N2STR 272
#define OFF2_W  0           // 128*272 = 34816
#define OFF2_XN 34816       // 64*272  = 17408
#define OFF2_T  52224       // 64*272  = 17408
#define OFF2_HM 69632       // 64*136*4 = 34816
#define SM_N2M  104448      // x2 = 208896 <= 227KB -> 2 CTA/SM

__global__ __launch_bounds__(512, 2) void k_node2mlp(const float* __restrict__ input,
                                                     const int* __restrict__ batch,
                                                     const float* __restrict__ b_out,
                                                     const float* __restrict__ b1,
                                                     const float* __restrict__ b2,
                                                     float* __restrict__ hout) {
    extern __shared__ __align__(16) char smem_raw[];
    const uint32_t smemU = (uint32_t)__cvta_generic_to_shared(smem_raw);
    const int tid = threadIdx.x;
    const int warp = tid >> 5, lane = tid & 31;
    const int g = lane >> 2, tg = lane & 3;
    const int wr = warp & 3, wq = warp >> 2;   // 4 M-blocks x 4 N-groups
    const int nb = blockIdx.x * N2TILE;
    char* xnb  = smem_raw + OFF2_XN;
    char* tb   = smem_raw + OFF2_T;
    float* hm_s = (float*)(smem_raw + OFF2_HM);

    const uint32_t a4 = ((lane & 7) + ((lane >> 3) & 1) * 8) * N2STR + ((lane >> 4) & 1) * 16;
    const uint32_t b4 = ((lane & 7) + ((lane >> 4) & 1) * 8) * N2STR + ((lane >> 3) & 1) * 16;
    const uint32_t aRow = wr * 16 * N2STR + a4;

    // fetch w_out -> W (single buffer)
    for (int i = tid; i < 2048; i += 512) {
        int n = i >> 4, k16 = i & 15;
        cp16(smemU + OFF2_W + n * N2STR + k16 * 16, pbO + n * 128 + k16 * 8);
    }
    CP_COMMIT();

    // stage A = o / wsum (bf16) into T
    for (int i = tid; i < N2TILE * 32; i += 512) {
        int r = i >> 5, c4 = i & 31;
        int n = nb + r;
        int nc = n < Nn ? n : Nn - 1;
        float4 o4 = ((const float4*)(g_o + (size_t)nc * Ff))[c4];
        int h = c4 >> 2;
        float inv = 1.f / (g_wsum[nc * Hh + h] + 1e-16f);
        *(uint32_t*)(tb + r * N2STR + c4 * 8)     = pack_bf16(o4.x * inv, o4.y * inv);
        *(uint32_t*)(tb + r * N2STR + c4 * 8 + 4) = pack_bf16(o4.z * inv, o4.w * inv);
    }
    CP_WAIT(0);
    __syncthreads();

    const int row0 = wr * 16 + g, row1 = row0 + 8;
    const int na = nb + row0, nb1 = nb + row1;
    const int nca = na < Nn ? na : Nn - 1;
    const int ncb = nb1 < Nn ? nb1 : Nn - 1;

    // GEMM: hm = (o/wsum) @ w_out  (warp covers 16 rows x 32 cols)
    {
        float d[4][4];
        #pragma unroll
        for (int i = 0; i < 4; i++) { d[i][0]=0.f; d[i][1]=0.f; d[i][2]=0.f; d[i][3]=0.f; }
        #pragma unroll
        for (int ks = 0; ks < 8; ks++) {
            uint32_t a0, a1, a2, a3;
            ldsm_x4(a0, a1, a2, a3, smemU + OFF2_T + aRow + ks * 32);
            #pragma unroll
            for (int np = 0; np < 2; np++) {
                int n0 = wq * 32 + np * 16;
                uint32_t b0, b1, b2, b3;
                ldsm_x4(b0, b1, b2, b3, smemU + OFF2_W + n0 * N2STR + b4 + ks * 32);
                mma_bf16(d[2 * np],     a0, a1, a2, a3, b0, b1);
                mma_bf16(d[2 * np + 1], a0, a1, a2, a3, b2, b3);
            }
        }
        #pragma unroll
        for (int nb2 = 0; nb2 < 4; nb2++) {
            int c = wq * 32 + nb2 * 8 + 2 * tg;
            float2 ia = *(const float2*)(input + (size_t)nca * Ff + c);
            float2 ib = *(const float2*)(input + (size_t)ncb * Ff + c);
            float bb0 = __ldg(b_out + c), bb1 = __ldg(b_out + c + 1);
            hm_s[row0 * 136 + c]     = d[nb2][0] + ia.x + bb0;
            hm_s[row0 * 136 + c + 1] = d[nb2][1] + ia.y + bb1;
            hm_s[row1 * 136 + c]     = d[nb2][2] + ib.x + bb0;
            hm_s[row1 * 136 + c + 1] = d[nb2][3] + ib.y + bb1;
        }
    }
    __syncthreads();

    // ada_ln(mlp) -> xn bf16 (each warp: 4 rows)
    #pragma unroll
    for (int q = 0; q < 4; q++) {
        int r = warp * 4 + q;
        int n = nb + r;
        int nc = n < Nn ? n : Nn - 1;
        float4 x = ((const float4*)(hm_s + r * 136))[lane];
        float s  = x.x + x.y + x.z + x.w;
        float ss = fmaf(x.x, x.x, fmaf(x.y, x.y, fmaf(x.z, x.z, x.w * x.w)));
        #pragma unroll
        for (int o = 16; o > 0; o >>= 1) {
            s  += __shfl_xor_sync(0xffffffffu, s, o);
            ss += __shfl_xor_sync(0xffffffffu, ss, o);
        }
        float mu = s * (1.f / Ff);
        float rstd = rsqrtf(ss * (1.f / Ff) - mu * mu + 1e-5f);
        int bix = batch[nc];
        const float* sb = g_sb_mlp + bix * F2;
        float4 sc = *((const float4*)(sb + lane * 4));
        float4 sh = *((const float4*)(sb + Ff + lane * 4));
        float o0 = (x.x - mu) * rstd * (1.f + sc.x) + sh.x;
        float o1 = (x.y - mu) * rstd * (1.f + sc.y) + sh.y;
        float o2 = (x.z - mu) * rstd * (1.f + sc.z) + sh.z;
        float o3 = (x.w - mu) * rstd * (1.f + sc.w) + sh.w;
        *(uint32_t*)(xnb + r * N2STR + lane * 8)     = pack_bf16(o0, o1);
        *(uint32_t*)(xnb + r * N2STR + lane * 8 + 4) = pack_bf16(o2, o3);
    }

    float oacc[4][4];
    #pragma unroll
    for (int i = 0; i < 4; i++) { oacc[i][0]=0.f; oacc[i][1]=0.f; oacc[i][2]=0.f; oacc[i][3]=0.f; }

    for (int ch = 0; ch < 4; ch++) {
        __syncthreads();   // xn visible / previous GEMM done with W
        for (int i = tid; i < 2048; i += 512) {
            int n = i >> 4, k16 = i & 15;
            cp16(smemU + OFF2_W + n * N2STR + k16 * 16,
                 pb1 + (size_t)ch * 128 * 128 + n * 128 + k16 * 8);
        }
        CP_COMMIT();
        CP_WAIT(0);
        __syncthreads();

        // GEMM dt = xn @ w1[ch]
        float dt[4][4];
        #pragma unroll
        for (int i = 0; i < 4; i++) { dt[i][0]=0.f; dt[i][1]=0.f; dt[i][2]=0.f; dt[i][3]=0.f; }
        #pragma unroll
        for (int ks = 0; ks < 8; ks++) {
            uint32_t a0, a1, a2, a3;
            ldsm_x4(a0, a1, a2, a3, smemU + OFF2_XN + aRow + ks * 32);
            #pragma unroll
            for (int np = 0; np < 2; np++) {
                int n0 = wq * 32 + np * 16;
                uint32_t b0, b1, b2, b3;
                ldsm_x4(b0, b1, b2, b3, smemU + OFF2_W + n0 * N2STR + b4 + ks * 32);
                mma_bf16(dt[2 * np],     a0, a1, a2, a3, b0, b1);
                mma_bf16(dt[2 * np + 1], a0, a1, a2, a3, b2, b3);
            }
        }
        #pragma unroll
        for (int nb2 = 0; nb2 < 4; nb2++) {
            int c = wq * 32 + nb2 * 8 + 2 * tg;
            float b10 = __ldg(b1 + ch * 128 + c), b11 = __ldg(b1 + ch * 128 + c + 1);
            *(uint32_t*)(tb + row0 * N2STR + c * 2) =
                pack_bf16(siluf(dt[nb2][0] + b10), siluf(dt[nb2][1] + b11));
            *(uint32_t*)(tb + row1 * N2STR + c * 2) =
                pack_bf16(siluf(dt[nb2][2] + b10), siluf(dt[nb2][3] + b11));
        }
        __syncthreads();   // T written; all warps done with W
        for (int i = tid; i < 2048; i += 512) {
            int n = i >> 4, k16 = i & 15;
            cp16(smemU + OFF2_W + n * N2STR + k16 * 16,
                 pb2 + n * 512 + ch * 128 + k16 * 8);
        }
        CP_COMMIT();
        CP_WAIT(0);
        __syncthreads();

        // GEMM oacc += T @ w2[ch]
        #pragma unroll
        for (int ks = 0; ks < 8; ks++) {
            uint32_t a0, a1, a2, a3;
            ldsm_x4(a0, a1, a2, a3, smemU + OFF2_T + aRow + ks * 32);
            #pragma unroll
            for (int np = 0; np < 2; np++) {
                int n0 = wq * 32 + np * 16;
                uint32_t b0, b1, b2, b3;
                ldsm_x4(b0, b1, b2, b3, smemU + OFF2_W + n0 * N2STR + b4 + ks * 32);
                mma_bf16(oacc[2 * np],     a0, a1, a2, a3, b0, b1);
                mma_bf16(oacc[2 * np + 1], a0, a1, a2, a3, b2, b3);
            }
        }
    }

    #pragma unroll
    for (int nb2 = 0; nb2 < 4; nb2++) {
        int c = wq * 32 + nb2 * 8 + 2 * tg;
        float b20 = __ldg(b2 + c), b21 = __ldg(b2 + c + 1);
        if (na < Nn) {
            float2 v = {oacc[nb2][0] + hm_s[row0 * 136 + c]     + b20,
                        oacc[nb2][1] + hm_s[row0 * 136 + c + 1] + b21};
            *(float2*)(hout + (size_t)na * Ff + c) = v;
        }
        if (nb1 < Nn) {
            float2 v = {oacc[nb2][2] + hm_s[row1 * 136 + c]     + b20,
                        oacc[nb2][3] + hm_s[row1 * 136 + c + 1] + b21};
            *(float2*)(hout + (size_t)nb1 * Ff + c) = v;
        }
    }
}

// ---------------- launcher ---------------------------------------------------------
extern "C" void kernel_launch(void* const* d_in, const int* in_sizes, int n_in,
                              void* d_out, int out_size) {
    const float* input     = (const float*)d_in[0];
    const float* cond      = (const float*)d_in[1];
    const float* a         = (const float*)d_in[2];
    const int*   batch     = (const int*)d_in[3];
    const int*   edges     = (const int*)d_in[4];
    const float* w_ada_mix = (const float*)d_in[5];
    const float* b_ada_mix = (const float*)d_in[6];
    const float* w_h       = (const float*)d_in[7];
    const float* b_h       = (const float*)d_in[8];
    const float* w_a       = (const float*)d_in[9];
    const float* w_vatt    = (const float*)d_in[10];
    const float* w_out     = (const float*)d_in[11];
    const float* b_out     = (const float*)d_in[12];
    const float* g_edge_p  = (const float*)d_in[13];
    const float* be_edge_p = (const float*)d_in[14];
    const float* w_edge    = (const float*)d_in[15];
    const float* b_edge    = (const float*)d_in[16];
    const float* w_ada_mlp = (const float*)d_in[17];
    const float* b_ada_mlp = (const float*)d_in[18];
    const float* w1        = (const float*)d_in[19];
    const float* b1        = (const float*)d_in[20];
    const float* w2        = (const float*)d_in[21];
    const float* b2        = (const float*)d_in[22];

    float* hout = (float*)d_out;                       // h: [N, F]
    float* aout = (float*)d_out + (size_t)Nn * Ff;     // a_out: [E, EF]

    cudaFuncSetAttribute(k_node1,    cudaFuncAttributeMaxDynamicSharedMemorySize, SM_NODE1);
    cudaFuncSetAttribute(k_edge,     cudaFuncAttributeMaxDynamicSharedMemorySize, SMEDGE);
    cudaFuncSetAttribute(k_node2mlp, cudaFuncAttributeMaxDynamicSharedMemorySize, SM_N2M);

    const int NT  = (Nn + NTILE - 1) / NTILE;    // 157
    const int NT2 = (Nn + N2TILE - 1) / N2TILE;  // 313

    k_setup<<<10240, 256>>>(w_h, w_out, w1, w2, cond,
                            w_ada_mix, b_ada_mix, w_ada_mlp, b_ada_mlp);
    k_node1<<<NT, 512, SM_NODE1>>>(input, batch, b_h);
    k_edge<<<296, 512, SMEDGE>>>(a, edges, w_a, w_vatt, w_edge,
                                 g_edge_p, be_edge_p, b_edge, aout);
    k_node2mlp<<<NT2, 512, SM_N2M>>>(input, batch, b_out, b1, b2, hout);
}